// round 4
// baseline (speedup 1.0000x reference)
#include <cuda_runtime.h>
#include <cstdint>

// Problem constants (fixed-shape problem)
#define MAXN 50000
#define KDEG 16

#define SIN 132   // s_in row stride (floats): 128 data + pad (bank-conflict-free frags)
#define SW  264   // s_w  row stride (floats): 256 data + pad

// ---------------- scratch (device globals: allocation-free) ----------------
__device__ float g_xp [MAXN * 64];
__device__ float g_h1 [MAXN * 64];
__device__ float g_h2 [MAXN * 128];
__device__ float g_t1 [MAXN * 192];
__device__ float g_t2 [MAXN * 64];

__device__ float g_wc1 [128 * 256];   // permuted+tf32 LSTM weights [k x pcol]
__device__ float g_wc2 [128 * 256];
__device__ float g_bs1 [256];
__device__ float g_bs2 [256];
__device__ float g_wo1 [128 * 64];
__device__ float g_wo2 [128 * 128];
__device__ float g_pT1 [64 * 64];
__device__ float g_pT2 [64 * 64];
__device__ float g_l1T [128 * 192];
__device__ float g_l2T [192 * 64];
__device__ float g_l3T [64 * 64];

// ---------------- helpers ----------------
// Accurate fast activations (EX2+RCP, ~2ulp): proven rel_err ~2e-5 path
__device__ __forceinline__ float sigf(float x) {
    return __fdividef(1.0f, 1.0f + __expf(-x));
}
__device__ __forceinline__ float tanhacc(float x) {
    return __fdividef(2.0f, 1.0f + __expf(-2.0f * x)) - 1.0f;
}
__device__ __forceinline__ float tf32r(float x) {
    uint32_t u;
    asm("cvt.rna.tf32.f32 %0, %1;" : "=r"(u) : "f"(x));
    return __uint_as_float(u);
}

#define MMA_TF32(D, A, b0, b1)                                                  \
    asm volatile("mma.sync.aligned.m16n8k8.row.col.f32.tf32.tf32.f32 "          \
                 "{%0,%1,%2,%3}, {%4,%5,%6,%7}, {%8,%9}, {%0,%1,%2,%3};"        \
                 : "+f"(D[0]), "+f"(D[1]), "+f"(D[2]), "+f"(D[3])               \
                 : "r"(A[0]), "r"(A[1]), "r"(A[2]), "r"(A[3]), "r"(b0), "r"(b1));

// per-half (128-thread) named barrier
#define BARG(id) asm volatile("bar.sync %0, 128;" :: "r"(id) : "memory")

// Gate-column permutation: each thread's accumulator fragment owns the full
// (i,f,g,o) quadruple for its hidden units -> c-state register-resident.
__device__ __forceinline__ int perm_orig_col(int p) {
    int nj = p >> 6, r = p & 63;
    int tp = r >> 4, r2 = r & 15;
    int half = r2 >> 3, r3 = r2 & 7;
    int q = r3 >> 1, low = r3 & 1;
    int gate = half * 2 + low;              // 0=i 1=f 2=g 3=o
    int jg = nj * 16 + q * 4 + tp;
    return gate * 64 + jg;
}

// ---------------- single fused prep kernel ----------------
__device__ __forceinline__ void prep_lstm_elem(float* wcat, float* bias, int idx,
                                               const float* wih, const float* whh,
                                               const float* bih, const float* bhh) {
    int k = idx >> 8, p = idx & 255;
    int g = perm_orig_col(p);
    float v = (k < 64) ? wih[g * 64 + k] : whh[g * 64 + (k - 64)];
    wcat[idx] = tf32r(v);
    if (idx < 256) {
        int g2 = perm_orig_col(idx);
        bias[idx] = bih[g2] + bhh[g2];
    }
}
__device__ __forceinline__ void prep_out_elem(float* woT, int idx,
                                              const float* llw, const float* lrw, int OUT) {
    int k = idx / OUT, o = idx - k * OUT;
    woT[idx] = tf32r((k < 64) ? lrw[o * 64 + k] : llw[o * 64 + (k - 64)]);
}
__device__ __forceinline__ void transpose_elem(float* dT, int idx,
                                               const float* w, int OUT, int IN) {
    int k = idx / OUT, o = idx - k * OUT;
    dT[idx] = tf32r(w[o * IN + k]);
}

__global__ void k_prep_all(
    float* wc1, float* bs1, const float* p1wih, const float* p1whh,
    const float* p1bih, const float* p1bhh,
    float* wc2, float* bs2, const float* p2wih, const float* p2whh,
    const float* p2bih, const float* p2bhh,
    float* wo1, const float* p1llw, const float* p1lrw,
    float* wo2, const float* p2llw, const float* p2lrw,
    float* pT1, const float* p1pw, float* pT2, const float* p2pw,
    float* l1T, const float* l1w, float* l2T, const float* l2w,
    float* l3T, const float* l3w) {
    int b = blockIdx.x, t = threadIdx.x;
    if (b < 128)       prep_lstm_elem(wc1, bs1, b * 256 + t, p1wih, p1whh, p1bih, p1bhh);
    else if (b < 256)  prep_lstm_elem(wc2, bs2, (b - 128) * 256 + t, p2wih, p2whh, p2bih, p2bhh);
    else if (b < 288)  prep_out_elem(wo1, (b - 256) * 256 + t, p1llw, p1lrw, 64);
    else if (b < 352)  prep_out_elem(wo2, (b - 288) * 256 + t, p2llw, p2lrw, 128);
    else if (b < 368)  transpose_elem(pT1, (b - 352) * 256 + t, p1pw, 64, 64);
    else if (b < 384)  transpose_elem(pT2, (b - 368) * 256 + t, p2pw, 64, 64);
    else if (b < 480)  transpose_elem(l1T, (b - 384) * 256 + t, l1w, 192, 128);
    else if (b < 528)  transpose_elem(l2T, (b - 480) * 256 + t, l2w, 64, 192);
    else               transpose_elem(l3T, (b - 528) * 256 + t, l3w, 64, 64);
}

__global__ void k_edge_copy(const int* __restrict__ ei, float* __restrict__ out, int count) {
    int i = blockIdx.x * blockDim.x + threadIdx.x;
    if (i < count) out[i] = (float)ei[i];
}

// ---------------- fused LSTM-SAGE kernel (tf32 mma.sync, M=128/block) ----------------
// Block = 128 nodes, 256 threads = 8 warps, warp grid 2(m64) x 4(n64).
// The two m-halves (warps 0-3 / 4-7) are independent recurrences coupled only
// through shared weight tiles; per-half named barriers let one half's MUFU
// activation phase overlap the other half's HMMA/LDS GEMM phase.
template<int OUT>
__global__ __launch_bounds__(256, 1)
void lstm_mma_kernel(const float* __restrict__ xp,
                     const float* __restrict__ xin,
                     const int*   __restrict__ src,
                     const float* __restrict__ wcat,
                     const float* __restrict__ bias,
                     const float* __restrict__ woT,   // [128 x OUT] tf32
                     const float* __restrict__ ob,
                     float* __restrict__ out,
                     int N) {
    extern __shared__ float sm[];
    float* s_w   = sm;                      // 128*SW
    float* s_in  = s_w + 128 * SW;          // 128*SIN ([x_t | h] rows)
    float* s_b   = s_in + 128 * SIN;        // 256
    int*   s_src = (int*)(s_b + 256);       // 2048

    const int tx = threadIdx.x;
    const int base = blockIdx.x * 128;
    const int lane = tx & 31, w = tx >> 5;
    const int mg = w >> 2, nj = w & 3;
    const int nwb = nj * 64;
    const int mrow = mg * 64;
    const int r = lane >> 2, q = lane & 3;
    const int wtid = tx & 127;              // tid within half
    const int barid = mg + 1;

    for (int i = tx; i < 128 * 64; i += 256) {
        int row = i >> 6, c4 = i & 63;
        ((float4*)&s_w[row * SW])[c4] = ((const float4*)wcat)[i];
    }
    s_b[tx] = bias[tx];
    for (int i = tx; i < 2048; i += 256) {
        int node = base + (i >> 4);
        s_src[i] = (node < N) ? src[node * KDEG + (i & 15)] : 0;
    }
    for (int i = tx; i < 128 * SIN; i += 256) s_in[i] = 0.f;
    __syncthreads();

    float bs0[8], bs1[8];
    #pragma unroll
    for (int nt = 0; nt < 8; nt++) {
        bs0[nt] = s_b[nwb + nt * 8 + 2 * q];
        bs1[nt] = s_b[nwb + nt * 8 + 2 * q + 1];
    }
    float cst[4][4][2];
    #pragma unroll
    for (int a = 0; a < 4; a++)
        #pragma unroll
        for (int b = 0; b < 4; b++) { cst[a][b][0] = 0.f; cst[a][b][1] = 0.f; }

    // per-half gather: 64 rows x 16 float4 = 1024 vec loads over 128 threads
    auto gather = [&](int t) {
        #pragma unroll
        for (int i = 0; i < 8; i++) {
            int idx = wtid + i * 128;
            int n = mrow + (idx >> 4), c4 = idx & 15;
            const float4 v = *(const float4*)(xp + (size_t)s_src[n * KDEG + t] * 64 + c4 * 4);
            float4 o;
            o.x = tf32r(v.x); o.y = tf32r(v.y); o.z = tf32r(v.z); o.w = tf32r(v.w);
            *(float4*)&s_in[n * SIN + c4 * 4] = o;
        }
    };

    gather(0);

    for (int t = 0; t < KDEG; t++) {
        BARG(barid);   // own half's gather + h writes visible

        float acc[4][8][4];
        #pragma unroll
        for (int mt = 0; mt < 4; mt++)
            #pragma unroll
            for (int nt = 0; nt < 8; nt++) {
                acc[mt][nt][0] = bs0[nt]; acc[mt][nt][1] = bs1[nt];
                acc[mt][nt][2] = bs0[nt]; acc[mt][nt][3] = bs1[nt];
            }

        #pragma unroll 2
        for (int kk = 0; kk < 128; kk += 8) {
            uint32_t afr[4][4];
            #pragma unroll
            for (int mt = 0; mt < 4; mt++) {
                const float* ap = s_in + (mrow + mt * 16 + r) * SIN + kk + q;
                afr[mt][0] = __float_as_uint(ap[0]);
                afr[mt][1] = __float_as_uint(ap[8 * SIN]);
                afr[mt][2] = __float_as_uint(ap[4]);
                afr[mt][3] = __float_as_uint(ap[8 * SIN + 4]);
            }
            #pragma unroll
            for (int nt = 0; nt < 8; nt++) {
                const float* bp = s_w + (kk + q) * SW + nwb + nt * 8 + r;
                uint32_t b0 = __float_as_uint(bp[0]);
                uint32_t b1 = __float_as_uint(bp[4 * SW]);
                MMA_TF32(acc[0][nt], afr[0], b0, b1);
                MMA_TF32(acc[1][nt], afr[1], b0, b1);
                MMA_TF32(acc[2][nt], afr[2], b0, b1);
                MMA_TF32(acc[3][nt], afr[3], b0, b1);
            }
        }
        BARG(barid);   // own half's s_in reads done

        if (t + 1 < KDEG) gather(t + 1);   // issue LDGs early; latency hides under MUFU

        // activation (accurate EX2-based)
        #pragma unroll
        for (int mt = 0; mt < 4; mt++) {
            #pragma unroll
            for (int tp = 0; tp < 4; tp++) {
                #pragma unroll
                for (int rr = 0; rr < 2; rr++) {
                    float iv = acc[mt][2 * tp][rr * 2 + 0];
                    float fv = acc[mt][2 * tp][rr * 2 + 1];
                    float gv = acc[mt][2 * tp + 1][rr * 2 + 0];
                    float ov = acc[mt][2 * tp + 1][rr * 2 + 1];
                    float c = sigf(fv) * cst[mt][tp][rr] + sigf(iv) * tanhacc(gv);
                    cst[mt][tp][rr] = c;
                    float h = sigf(ov) * tanhacc(c);
                    int row = mrow + mt * 16 + r + 8 * rr;
                    s_in[row * SIN + 64 + nj * 16 + q * 4 + tp] = tf32r(h);
                }
            }
        }
    }
    __syncthreads();   // both halves done with s_w before overwrite

    // ---- fused SAGE output via MMA: out = relu([x || h] * woT + ob) ----
    constexpr int NT2 = OUT / 32;
    const int NPJ = OUT / 4;
    const int nwb2 = nj * NPJ;

    for (int i = tx; i < 128 * (OUT / 4); i += 256) {
        int row = i / (OUT / 4), c4 = i % (OUT / 4);
        ((float4*)&s_w[row * SW])[c4] = ((const float4*)woT)[i];
    }
    for (int i = tx; i < OUT; i += 256) s_b[i] = ob[i];
    #pragma unroll
    for (int i = 0; i < 8; i++) {
        int idx = tx + i * 256;
        int n = idx >> 4, c4 = idx & 15;
        int node = base + n;
        float4 v = make_float4(0.f, 0.f, 0.f, 0.f);
        if (node < N) v = *(const float4*)(xin + (size_t)node * 64 + c4 * 4);
        float4 o;
        o.x = tf32r(v.x); o.y = tf32r(v.y); o.z = tf32r(v.z); o.w = tf32r(v.w);
        *(float4*)&s_in[n * SIN + c4 * 4] = o;
    }
    __syncthreads();

    float a2[4][NT2][4];
    #pragma unroll
    for (int mt = 0; mt < 4; mt++)
        #pragma unroll
        for (int nt = 0; nt < NT2; nt++) {
            int c0 = nwb2 + nt * 8 + 2 * q;
            a2[mt][nt][0] = s_b[c0];     a2[mt][nt][1] = s_b[c0 + 1];
            a2[mt][nt][2] = s_b[c0];     a2[mt][nt][3] = s_b[c0 + 1];
        }
    #pragma unroll 4
    for (int kk = 0; kk < 128; kk += 8) {
        uint32_t afr[4][4];
        #pragma unroll
        for (int mt = 0; mt < 4; mt++) {
            const float* ap = s_in + (mrow + mt * 16 + r) * SIN + kk + q;
            afr[mt][0] = __float_as_uint(ap[0]);
            afr[mt][1] = __float_as_uint(ap[8 * SIN]);
            afr[mt][2] = __float_as_uint(ap[4]);
            afr[mt][3] = __float_as_uint(ap[8 * SIN + 4]);
        }
        #pragma unroll
        for (int nt = 0; nt < NT2; nt++) {
            const float* bp = s_w + (kk + q) * SW + nwb2 + nt * 8 + r;
            uint32_t b0 = __float_as_uint(bp[0]);
            uint32_t b1 = __float_as_uint(bp[4 * SW]);
            MMA_TF32(a2[0][nt], afr[0], b0, b1);
            MMA_TF32(a2[1][nt], afr[1], b0, b1);
            MMA_TF32(a2[2][nt], afr[2], b0, b1);
            MMA_TF32(a2[3][nt], afr[3], b0, b1);
        }
    }
    #pragma unroll
    for (int mt = 0; mt < 4; mt++)
        #pragma unroll
        for (int nt = 0; nt < NT2; nt++)
            #pragma unroll
            for (int rr = 0; rr < 2; rr++) {
                int node = base + mrow + mt * 16 + r + 8 * rr;
                if (node < N) {
                    int c0 = nwb2 + nt * 8 + 2 * q;
                    float2 v;
                    v.x = fmaxf(a2[mt][nt][2 * rr + 0], 0.f);
                    v.y = fmaxf(a2[mt][nt][2 * rr + 1], 0.f);
                    *(float2*)(out + (size_t)node * OUT + c0) = v;
                }
            }
}

// ---------------- tf32 MMA linear+relu ----------------
template<int KIN, int KOUT>
__global__ __launch_bounds__(256, 1)
void mma_linear(const float* __restrict__ A, const float* __restrict__ WT,
                const float* __restrict__ b, float* __restrict__ out, int N) {
    constexpr int SINL = KIN + 4, SWL = KOUT + 8;
    constexpr int NT = KOUT / 32, NPJ = KOUT / 4;
    extern __shared__ float sm[];
    float* s_w  = sm;
    float* s_in = s_w + KIN * SWL;
    float* s_b  = s_in + 128 * SINL;

    const int tx = threadIdx.x, base = blockIdx.x * 128;
    const int lane = tx & 31, w = tx >> 5;
    const int mg = w >> 2, nj = w & 3;
    const int r = lane >> 2, q = lane & 3;
    const int mrow = mg * 64, nwb = nj * NPJ;

    for (int i = tx; i < KIN * (KOUT / 4); i += 256) {
        int row = i / (KOUT / 4), c4 = i % (KOUT / 4);
        ((float4*)&s_w[row * SWL])[c4] = ((const float4*)WT)[i];
    }
    for (int i = tx; i < KOUT; i += 256) s_b[i] = b[i];
    for (int i = tx; i < 128 * (KIN / 4); i += 256) {
        int n = i / (KIN / 4), c4 = i % (KIN / 4);
        int node = base + n;
        float4 v = make_float4(0.f, 0.f, 0.f, 0.f);
        if (node < N) v = *(const float4*)(A + (size_t)node * KIN + c4 * 4);
        float4 o;
        o.x = tf32r(v.x); o.y = tf32r(v.y); o.z = tf32r(v.z); o.w = tf32r(v.w);
        *(float4*)&s_in[n * SINL + c4 * 4] = o;
    }
    __syncthreads();

    float acc[4][NT][4];
    #pragma unroll
    for (int mt = 0; mt < 4; mt++)
        #pragma unroll
        for (int nt = 0; nt < NT; nt++) {
            int c0 = nwb + nt * 8 + 2 * q;
            acc[mt][nt][0] = s_b[c0];     acc[mt][nt][1] = s_b[c0 + 1];
            acc[mt][nt][2] = s_b[c0];     acc[mt][nt][3] = s_b[c0 + 1];
        }
    #pragma unroll 4
    for (int kk = 0; kk < KIN; kk += 8) {
        uint32_t afr[4][4];
        #pragma unroll
        for (int mt = 0; mt < 4; mt++) {
            const float* ap = s_in + (mrow + mt * 16 + r) * SINL + kk + q;
            afr[mt][0] = __float_as_uint(ap[0]);
            afr[mt][1] = __float_as_uint(ap[8 * SINL]);
            afr[mt][2] = __float_as_uint(ap[4]);
            afr[mt][3] = __float_as_uint(ap[8 * SINL + 4]);
        }
        #pragma unroll
        for (int nt = 0; nt < NT; nt++) {
            const float* bp = s_w + (kk + q) * SWL + nwb + nt * 8 + r;
            uint32_t b0 = __float_as_uint(bp[0]);
            uint32_t b1 = __float_as_uint(bp[4 * SWL]);
            MMA_TF32(acc[0][nt], afr[0], b0, b1);
            MMA_TF32(acc[1][nt], afr[1], b0, b1);
            MMA_TF32(acc[2][nt], afr[2], b0, b1);
            MMA_TF32(acc[3][nt], afr[3], b0, b1);
        }
    }
    #pragma unroll
    for (int mt = 0; mt < 4; mt++)
        #pragma unroll
        for (int nt = 0; nt < NT; nt++)
            #pragma unroll
            for (int rr = 0; rr < 2; rr++) {
                int node = base + mrow + mt * 16 + r + 8 * rr;
                if (node < N) {
                    int c0 = nwb + nt * 8 + 2 * q;
                    float2 v;
                    v.x = fmaxf(acc[mt][nt][2 * rr + 0], 0.f);
                    v.y = fmaxf(acc[mt][nt][2 * rr + 1], 0.f);
                    *(float2*)(out + (size_t)node * KOUT + c0) = v;
                }
            }
}

// ---------------- host launcher ----------------
static void* symaddr(const void* sym) {
    void* p = nullptr;
    cudaGetSymbolAddress(&p, sym);
    return p;
}

extern "C" void kernel_launch(void* const* d_in, const int* in_sizes, int n_in,
                              void* d_out, int out_size) {
    const float* x   = (const float*)d_in[0];
    const int*   ei  = (const int*)d_in[1];
    const int N = in_sizes[0] / 64;
    const int E = in_sizes[1] / 2;
    const int* src = ei;

    const float* p1pw  = (const float*)d_in[3];
    const float* p1pb  = (const float*)d_in[4];
    const float* p1wih = (const float*)d_in[5];
    const float* p1whh = (const float*)d_in[6];
    const float* p1bih = (const float*)d_in[7];
    const float* p1bhh = (const float*)d_in[8];
    const float* p1llw = (const float*)d_in[9];
    const float* p1llb = (const float*)d_in[10];
    const float* p1lrw = (const float*)d_in[11];
    const float* p2pw  = (const float*)d_in[12];
    const float* p2pb  = (const float*)d_in[13];
    const float* p2wih = (const float*)d_in[14];
    const float* p2whh = (const float*)d_in[15];
    const float* p2bih = (const float*)d_in[16];
    const float* p2bhh = (const float*)d_in[17];
    const float* p2llw = (const float*)d_in[18];
    const float* p2llb = (const float*)d_in[19];
    const float* p2lrw = (const float*)d_in[20];
    const float* l1w   = (const float*)d_in[21];
    const float* l1b   = (const float*)d_in[22];
    const float* l2w   = (const float*)d_in[23];
    const float* l2b   = (const float*)d_in[24];
    const float* l3w   = (const float*)d_in[25];
    const float* l3b   = (const float*)d_in[26];

    float* xp  = (float*)symaddr(g_xp);
    float* h1  = (float*)symaddr(g_h1);
    float* h2  = (float*)symaddr(g_h2);
    float* t1  = (float*)symaddr(g_t1);
    float* t2  = (float*)symaddr(g_t2);
    float* wc1 = (float*)symaddr(g_wc1);
    float* wc2 = (float*)symaddr(g_wc2);
    float* bs1 = (float*)symaddr(g_bs1);
    float* bs2 = (float*)symaddr(g_bs2);
    float* wo1 = (float*)symaddr(g_wo1);
    float* wo2 = (float*)symaddr(g_wo2);
    float* pT1 = (float*)symaddr(g_pT1);
    float* pT2 = (float*)symaddr(g_pT2);
    float* l1T = (float*)symaddr(g_l1T);
    float* l2T = (float*)symaddr(g_l2T);
    float* l3T = (float*)symaddr(g_l3T);

    const int SM_LSTM = (128 * SW + 128 * SIN + 256) * 4 + 2048 * 4;   // 211968
    const int SM_6464 = (64 * 72 + 128 * 68 + 64) * 4;
    const int SM_L1   = (128 * 200 + 128 * 132 + 192) * 4;
    const int SM_L2   = (192 * 72 + 128 * 196 + 64) * 4;
    cudaFuncSetAttribute(lstm_mma_kernel<64>,  cudaFuncAttributeMaxDynamicSharedMemorySize, SM_LSTM);
    cudaFuncSetAttribute(lstm_mma_kernel<128>, cudaFuncAttributeMaxDynamicSharedMemorySize, SM_LSTM);
    cudaFuncSetAttribute(mma_linear<64, 64>,   cudaFuncAttributeMaxDynamicSharedMemorySize, SM_6464);
    cudaFuncSetAttribute(mma_linear<128, 192>, cudaFuncAttributeMaxDynamicSharedMemorySize, SM_L1);
    cudaFuncSetAttribute(mma_linear<192, 64>,  cudaFuncAttributeMaxDynamicSharedMemorySize, SM_L2);

    // --- fused weight prep (single launch) ---
    k_prep_all<<<544, 256>>>(wc1, bs1, p1wih, p1whh, p1bih, p1bhh,
                             wc2, bs2, p2wih, p2whh, p2bih, p2bhh,
                             wo1, p1llw, p1lrw, wo2, p2llw, p2lrw,
                             pT1, p1pw, pT2, p2pw,
                             l1T, l1w, l2T, l2w, l3T, l3w);

    const int NB = (N + 127) / 128;

    // --- layer 1 ---
    mma_linear<64, 64><<<NB, 256, SM_6464>>>(x, pT1, p1pb, xp, N);
    lstm_mma_kernel<64><<<NB, 256, SM_LSTM>>>(xp, x, src, wc1, bs1, wo1, p1llb, h1, N);
    // --- layer 2 ---
    mma_linear<64, 64><<<NB, 256, SM_6464>>>(h1, pT2, p2pb, xp, N);
    lstm_mma_kernel<128><<<NB, 256, SM_LSTM>>>(xp, h1, src, wc2, bs2, wo2, p2llb, h2, N);
    // --- MLP head ---
    mma_linear<128, 192><<<NB, 256, SM_L1>>>(h2, l1T, l1b, t1, N);
    mma_linear<192, 64><<<NB, 256, SM_L2>>>(t1, l2T, l2b, t2, N);
    mma_linear<64, 64><<<NB, 256, SM_6464>>>(t2, l3T, l3b, (float*)d_out, N);

    // --- edge_index passthrough if the output buffer holds it ---
    long hsz = (long)N * 64;
    if ((long)out_size > hsz) {
        long remaining = (long)out_size - hsz;
        int count = (int)((remaining < (long)2 * E) ? remaining : (long)2 * E);
        k_edge_copy<<<(count + 255) / 256, 256>>>(ei, (float*)d_out + hsz, count);
    }
}

// round 5
// speedup vs baseline: 2.0639x; 2.0639x over previous
#include <cuda_runtime.h>
#include <cuda_fp16.h>
#include <cstdint>

// Problem constants (fixed-shape problem)
#define MAXN 50000
#define KDEG 16

// half strides: pad 8 halves (16B) -> word-stride ≡ 4 (mod 32) -> conflict-free frags
#define KH128 136
#define WS128 68

// ---------------- scratch (device globals: allocation-free) ----------------
__device__ __half g_xp [MAXN * 64];    // projected feats, fp16
__device__ float  g_h1 [MAXN * 64];
__device__ float  g_h2 [MAXN * 128];
__device__ float  g_t1 [MAXN * 192];
__device__ float  g_t2 [MAXN * 64];

__device__ __half g_wc1 [256 * 128];   // permuted LSTM weights [pcol][k], fp16
__device__ __half g_wc2 [256 * 128];
__device__ float  g_bs1 [256];
__device__ float  g_bs2 [256];
__device__ __half g_wo1h[64 * 128],  g_wo1l[64 * 128];    // SAGE out [o][k] hi/lo
__device__ __half g_wo2h[128 * 128], g_wo2l[128 * 128];
__device__ __half g_pT1h[64 * 64],   g_pT1l[64 * 64];     // [o][k] hi/lo (torch layout!)
__device__ __half g_pT2h[64 * 64],   g_pT2l[64 * 64];
__device__ __half g_l1h [192 * 128], g_l1l [192 * 128];
__device__ __half g_l2h [64 * 192],  g_l2l [64 * 192];
__device__ __half g_l3h [64 * 64],   g_l3l [64 * 64];

// ---------------- helpers ----------------
__device__ __forceinline__ float tanha(float x) {
    float y;
    asm("tanh.approx.f32 %0, %1;" : "=f"(y) : "f"(x));
    return y;
}
__device__ __forceinline__ float sigt(float x) {
    return fmaf(tanha(0.5f * x), 0.5f, 0.5f);
}

#define MMA_F16(D, A, b0, b1)                                                   \
    asm volatile("mma.sync.aligned.m16n8k16.row.col.f32.f16.f16.f32 "           \
                 "{%0,%1,%2,%3}, {%4,%5,%6,%7}, {%8,%9}, {%0,%1,%2,%3};"        \
                 : "+f"(D[0]), "+f"(D[1]), "+f"(D[2]), "+f"(D[3])               \
                 : "r"(A[0]), "r"(A[1]), "r"(A[2]), "r"(A[3]), "r"(b0), "r"(b1));

// Gate-column permutation: each thread's accumulator fragment owns the full
// (i,f,g,o) quadruple for its hidden units (accumulator col map identical k8/k16).
__device__ __forceinline__ int perm_orig_col(int p) {
    int nj = p >> 6, rr = p & 63;
    int tp = rr >> 4, r2 = rr & 15;
    int half_ = r2 >> 3, r3 = r2 & 7;
    int q = r3 >> 1, low = r3 & 1;
    int gate = half_ * 2 + low;             // 0=i 1=f 2=g 3=o
    int jg = nj * 16 + q * 4 + tp;
    return gate * 64 + jg;
}

__device__ __forceinline__ void wsplit(__half* hi, __half* lo, int idx, float v) {
    __half h = __float2half_rn(v);
    hi[idx] = h;
    lo[idx] = __float2half_rn(v - __half2float(h));
}

// ---------------- single fused prep kernel ----------------
__global__ void k_prep_all(
    const float* p1wih, const float* p1whh, const float* p1bih, const float* p1bhh,
    const float* p2wih, const float* p2whh, const float* p2bih, const float* p2bhh,
    const float* p1llw, const float* p1lrw, const float* p2llw, const float* p2lrw,
    const float* p1pw, const float* p2pw,
    const float* l1w, const float* l2w, const float* l3w) {
    int b = blockIdx.x, t = threadIdx.x;
    if (b < 128) {                       // wc1: 256x128 halves
        int idx = b * 256 + t;
        int p = idx >> 7, k = idx & 127;
        int g = perm_orig_col(p);
        g_wc1[idx] = __float2half_rn(k < 64 ? p1wih[g * 64 + k] : p1whh[g * 64 + (k - 64)]);
        if (idx < 256) { int g2 = perm_orig_col(idx); g_bs1[idx] = p1bih[g2] + p1bhh[g2]; }
    } else if (b < 256) {                // wc2
        int idx = (b - 128) * 256 + t;
        int p = idx >> 7, k = idx & 127;
        int g = perm_orig_col(p);
        g_wc2[idx] = __float2half_rn(k < 64 ? p2wih[g * 64 + k] : p2whh[g * 64 + (k - 64)]);
        if (idx < 256) { int g2 = perm_orig_col(idx); g_bs2[idx] = p2bih[g2] + p2bhh[g2]; }
    } else if (b < 288) {                // wo1: 64x128
        int idx = (b - 256) * 256 + t;
        int o = idx >> 7, k = idx & 127;
        wsplit(g_wo1h, g_wo1l, idx, k < 64 ? p1lrw[o * 64 + k] : p1llw[o * 64 + (k - 64)]);
    } else if (b < 352) {                // wo2: 128x128
        int idx = (b - 288) * 256 + t;
        int o = idx >> 7, k = idx & 127;
        wsplit(g_wo2h, g_wo2l, idx, k < 64 ? p2lrw[o * 64 + k] : p2llw[o * 64 + (k - 64)]);
    } else if (b < 368) {                // pT1: 64x64 (direct torch layout)
        int idx = (b - 352) * 256 + t;
        wsplit(g_pT1h, g_pT1l, idx, p1pw[idx]);
    } else if (b < 384) {                // pT2
        int idx = (b - 368) * 256 + t;
        wsplit(g_pT2h, g_pT2l, idx, p2pw[idx]);
    } else if (b < 480) {                // l1: 192x128
        int idx = (b - 384) * 256 + t;
        wsplit(g_l1h, g_l1l, idx, l1w[idx]);
    } else if (b < 528) {                // l2: 64x192
        int idx = (b - 480) * 256 + t;
        wsplit(g_l2h, g_l2l, idx, l2w[idx]);
    } else {                             // l3: 64x64
        int idx = (b - 528) * 256 + t;
        wsplit(g_l3h, g_l3l, idx, l3w[idx]);
    }
}

__global__ void k_edge_copy(const int* __restrict__ ei, float* __restrict__ out, int count) {
    int i = blockIdx.x * blockDim.x + threadIdx.x;
    if (i < count) out[i] = (float)ei[i];
}

// ---------------- fused LSTM-SAGE kernel (fp16 m16n8k16) ----------------
// Block = 128 nodes, 256 threads = 8 warps, warp grid 2(m64) x 4(n64).
template<int OUT>
__global__ __launch_bounds__(256, 1)
void lstm_mma_kernel(const __half* __restrict__ xp,
                     const float*  __restrict__ xin,
                     const int*    __restrict__ src,
                     const __half* __restrict__ wcat,   // [256][128] permuted
                     const float*  __restrict__ bias,   // [256] permuted
                     const __half* __restrict__ wohi,   // [OUT][128]
                     const __half* __restrict__ wolo,
                     const float*  __restrict__ ob,
                     float* __restrict__ out,
                     int N) {
    extern __shared__ __half smh[];
    __half* s_w   = smh;                        // 256*KH128 (LSTM W; reused for wo hi/lo)
    __half* s_in  = s_w + 256 * KH128;          // 128*KH128 : [x_t | h] (hi plane)
    __half* s_lo  = s_in + 128 * KH128;         // 128*KH128 : epilogue lo plane
    float*  s_b   = (float*)(s_lo + 128 * KH128);   // 256
    int*    s_src = (int*)(s_b + 256);          // 2048

    const int tx = threadIdx.x;
    const int base = blockIdx.x * 128;
    const int lane = tx & 31, w = tx >> 5;
    const int mg = w >> 2, nj = w & 3;
    const int nwb = nj * 64;
    const int mrow = mg * 64;
    const int r = lane >> 2, q = lane & 3;

    // LSTM weights -> smem [p][k], padded rows (row bytes = 272, 16B-aligned)
    for (int i = tx; i < 4096; i += 256) {               // 256 rows * 16 uint4
        int row = i >> 4, c = i & 15;
        ((uint4*)(s_w + row * KH128))[c] = ((const uint4*)wcat)[i];
    }
    s_b[tx] = bias[tx];
    for (int i = tx; i < 2048; i += 256) {
        int node = base + (i >> 4);
        s_src[i] = (node < N) ? src[node * KDEG + (i & 15)] : 0;
    }
    // zero s_in (h cols start at 0) and s_lo (epilogue lo plane, h cols stay 0)
    for (int i = tx; i < (128 * KH128) / 4; i += 256) {
        ((uint2*)s_in)[i] = make_uint2(0u, 0u);
        ((uint2*)s_lo)[i] = make_uint2(0u, 0u);
    }
    __syncthreads();

    float bs0[8], bs1[8];
    #pragma unroll
    for (int nt = 0; nt < 8; nt++) {
        bs0[nt] = s_b[nwb + nt * 8 + 2 * q];
        bs1[nt] = s_b[nwb + nt * 8 + 2 * q + 1];
    }
    float cst[4][4][2];
    #pragma unroll
    for (int a = 0; a < 4; a++)
        #pragma unroll
        for (int bb = 0; bb < 4; bb++) { cst[a][bb][0] = 0.f; cst[a][bb][1] = 0.f; }

    // gather x_t (fp16 copy, 8B chunks): 128 rows * 16 uint2
    auto gather = [&](int t) {
        #pragma unroll
        for (int i = 0; i < 8; i++) {
            int idx = tx + i * 256;
            int n = idx >> 4, c = idx & 15;
            uint2 v = *(const uint2*)(xp + (size_t)s_src[n * KDEG + t] * 64 + c * 4);
            *(uint2*)(s_in + n * KH128 + c * 4) = v;
        }
    };

    gather(0);

    for (int t = 0; t < KDEG; t++) {
        __syncthreads();   // gather + h writes visible

        float acc[4][8][4];
        #pragma unroll
        for (int mt = 0; mt < 4; mt++)
            #pragma unroll
            for (int nt = 0; nt < 8; nt++) {
                acc[mt][nt][0] = bs0[nt]; acc[mt][nt][1] = bs1[nt];
                acc[mt][nt][2] = bs0[nt]; acc[mt][nt][3] = bs1[nt];
            }

        #pragma unroll 2
        for (int kc = 0; kc < 8; kc++) {           // K chunks of 16
            const int kw = kc * 8;                 // word offset
            uint32_t afr[4][4];
            #pragma unroll
            for (int mt = 0; mt < 4; mt++) {
                const uint32_t* ap = (const uint32_t*)s_in + (mrow + mt * 16 + r) * WS128 + kw + q;
                afr[mt][0] = ap[0];
                afr[mt][1] = ap[8 * WS128];
                afr[mt][2] = ap[4];
                afr[mt][3] = ap[8 * WS128 + 4];
            }
            #pragma unroll
            for (int nt = 0; nt < 8; nt++) {
                const uint32_t* bp = (const uint32_t*)s_w + (nwb + nt * 8 + r) * WS128 + kw + q;
                uint32_t b0 = bp[0], b1 = bp[4];
                MMA_F16(acc[0][nt], afr[0], b0, b1);
                MMA_F16(acc[1][nt], afr[1], b0, b1);
                MMA_F16(acc[2][nt], afr[2], b0, b1);
                MMA_F16(acc[3][nt], afr[3], b0, b1);
            }
        }
        __syncthreads();   // s_in reads done

        // activation + h writeback (fp16x4 packed)
        #pragma unroll
        for (int mt = 0; mt < 4; mt++) {
            #pragma unroll
            for (int rr = 0; rr < 2; rr++) {
                float hv[4];
                #pragma unroll
                for (int tp = 0; tp < 4; tp++) {
                    float iv = acc[mt][2 * tp][rr * 2 + 0];
                    float fv = acc[mt][2 * tp][rr * 2 + 1];
                    float gv = acc[mt][2 * tp + 1][rr * 2 + 0];
                    float ov = acc[mt][2 * tp + 1][rr * 2 + 1];
                    float c = sigt(fv) * cst[mt][tp][rr] + sigt(iv) * tanha(gv);
                    cst[mt][tp][rr] = c;
                    hv[tp] = sigt(ov) * tanha(c);
                }
                int row = mrow + mt * 16 + r + 8 * rr;
                __half2* dst = (__half2*)(s_in + row * KH128 + 64 + nj * 16 + q * 4);
                dst[0] = __floats2half2_rn(hv[0], hv[1]);
                dst[1] = __floats2half2_rn(hv[2], hv[3]);
            }
        }
        if (t + 1 < KDEG) gather(t + 1);   // x cols, disjoint from h cols
    }
    __syncthreads();   // all s_w reads done before overwrite

    // ---- fused SAGE output, split fp16: out = relu([x||h]*Wo^T + ob) ----
    constexpr int NT2 = OUT / 32;
    const int nwb2 = nj * (OUT / 4);
    __half* s_wlo = s_w + OUT * KH128;

    for (int i = tx; i < OUT * 16; i += 256) {           // OUT rows * 16 uint4
        int row = i >> 4, c = i & 15;
        ((uint4*)(s_w + row * KH128))[c]   = ((const uint4*)wohi)[i];
        ((uint4*)(s_wlo + row * KH128))[c] = ((const uint4*)wolo)[i];
    }
    for (int i = tx; i < OUT; i += 256) s_b[i] = ob[i];
    // xin -> hi/lo planes (x cols 0..63); h cols: hi already in s_in, lo zero
    #pragma unroll
    for (int i = 0; i < 8; i++) {
        int idx = tx + i * 256;                          // 128 rows * 16 float4
        int n = idx >> 4, c = idx & 15;
        int node = base + n;
        float4 v = make_float4(0.f, 0.f, 0.f, 0.f);
        if (node < N) v = ((const float4*)(xin + (size_t)node * 64))[c];
        __half2 h0 = __floats2half2_rn(v.x, v.y), h1 = __floats2half2_rn(v.z, v.w);
        float2 f0 = __half22float2(h0), f1 = __half22float2(h1);
        __half2 l0 = __floats2half2_rn(v.x - f0.x, v.y - f0.y);
        __half2 l1 = __floats2half2_rn(v.z - f1.x, v.w - f1.y);
        __half2* dh = (__half2*)(s_in + n * KH128 + c * 4);
        __half2* dl = (__half2*)(s_lo + n * KH128 + c * 4);
        dh[0] = h0; dh[1] = h1;
        dl[0] = l0; dl[1] = l1;
    }
    __syncthreads();

    float a2[4][NT2][4];
    #pragma unroll
    for (int mt = 0; mt < 4; mt++)
        #pragma unroll
        for (int nt = 0; nt < NT2; nt++) {
            int c0 = nwb2 + nt * 8 + 2 * q;
            a2[mt][nt][0] = s_b[c0];     a2[mt][nt][1] = s_b[c0 + 1];
            a2[mt][nt][2] = s_b[c0];     a2[mt][nt][3] = s_b[c0 + 1];
        }
    #pragma unroll 2
    for (int kc = 0; kc < 8; kc++) {
        const int kw = kc * 8;
        uint32_t ah[4][4], al[4][4];
        #pragma unroll
        for (int mt = 0; mt < 4; mt++) {
            const uint32_t* ap = (const uint32_t*)s_in + (mrow + mt * 16 + r) * WS128 + kw + q;
            const uint32_t* lp = (const uint32_t*)s_lo + (mrow + mt * 16 + r) * WS128 + kw + q;
            ah[mt][0] = ap[0]; ah[mt][1] = ap[8 * WS128]; ah[mt][2] = ap[4]; ah[mt][3] = ap[8 * WS128 + 4];
            al[mt][0] = lp[0]; al[mt][1] = lp[8 * WS128]; al[mt][2] = lp[4]; al[mt][3] = lp[8 * WS128 + 4];
        }
        #pragma unroll
        for (int nt = 0; nt < NT2; nt++) {
            const uint32_t* bh = (const uint32_t*)s_w   + (nwb2 + nt * 8 + r) * WS128 + kw + q;
            const uint32_t* bl = (const uint32_t*)s_wlo + (nwb2 + nt * 8 + r) * WS128 + kw + q;
            uint32_t bh0 = bh[0], bh1 = bh[4], bl0 = bl[0], bl1 = bl[4];
            #pragma unroll
            for (int mt = 0; mt < 4; mt++) {
                MMA_F16(a2[mt][nt], ah[mt], bh0, bh1);
                MMA_F16(a2[mt][nt], ah[mt], bl0, bl1);
                MMA_F16(a2[mt][nt], al[mt], bh0, bh1);
            }
        }
    }
    #pragma unroll
    for (int mt = 0; mt < 4; mt++)
        #pragma unroll
        for (int nt = 0; nt < NT2; nt++)
            #pragma unroll
            for (int rr = 0; rr < 2; rr++) {
                int node = base + mrow + mt * 16 + r + 8 * rr;
                if (node < N) {
                    int c0 = nwb2 + nt * 8 + 2 * q;
                    float2 v;
                    v.x = fmaxf(a2[mt][nt][2 * rr + 0], 0.f);
                    v.y = fmaxf(a2[mt][nt][2 * rr + 1], 0.f);
                    *(float2*)(out + (size_t)node * OUT + c0) = v;
                }
            }
}

// ---------------- split-fp16 MMA linear + relu ----------------
template<int KIN, int KOUT, bool HOUT>
__global__ __launch_bounds__(256, 1)
void mma_linear(const float* __restrict__ A,
                const __half* __restrict__ Whi, const __half* __restrict__ Wlo,
                const float* __restrict__ bias, void* __restrict__ outp, int N) {
    constexpr int KH = KIN + 8, WSL = KH / 2, CH = KIN / 16;
    constexpr int NT = KOUT / 32;
    extern __shared__ __half sh[];
    __half* s_wh = sh;                        // KOUT*KH
    __half* s_wl = s_wh + KOUT * KH;
    __half* s_ah = s_wl + KOUT * KH;          // 128*KH
    __half* s_al = s_ah + 128 * KH;
    float*  s_b  = (float*)(s_al + 128 * KH);

    const int tx = threadIdx.x, base = blockIdx.x * 128;
    const int lane = tx & 31, w = tx >> 5;
    const int mg = w >> 2, nj = w & 3;
    const int r = lane >> 2, q = lane & 3;
    const int mrow = mg * 64, nwb = nj * (KOUT / 4);

    for (int i = tx; i < KOUT * (KIN / 8); i += 256) {
        int row = i / (KIN / 8), c = i % (KIN / 8);
        ((uint4*)(s_wh + row * KH))[c] = ((const uint4*)Whi)[i];
        ((uint4*)(s_wl + row * KH))[c] = ((const uint4*)Wlo)[i];
    }
    for (int i = tx; i < KOUT; i += 256) s_b[i] = bias[i];
    for (int i = tx; i < 128 * (KIN / 4); i += 256) {
        int n = i / (KIN / 4), c = i % (KIN / 4);
        int node = base + n;
        float4 v = make_float4(0.f, 0.f, 0.f, 0.f);
        if (node < N) v = ((const float4*)(A + (size_t)node * KIN))[c];
        __half2 h0 = __floats2half2_rn(v.x, v.y), h1 = __floats2half2_rn(v.z, v.w);
        float2 f0 = __half22float2(h0), f1 = __half22float2(h1);
        __half2* dh = (__half2*)(s_ah + n * KH + c * 4);
        __half2* dl = (__half2*)(s_al + n * KH + c * 4);
        dh[0] = h0; dh[1] = h1;
        dl[0] = __floats2half2_rn(v.x - f0.x, v.y - f0.y);
        dl[1] = __floats2half2_rn(v.z - f1.x, v.w - f1.y);
    }
    __syncthreads();

    float acc[4][NT][4];
    #pragma unroll
    for (int mt = 0; mt < 4; mt++)
        #pragma unroll
        for (int nt = 0; nt < NT; nt++) {
            int c0 = nwb + nt * 8 + 2 * q;
            acc[mt][nt][0] = s_b[c0];     acc[mt][nt][1] = s_b[c0 + 1];
            acc[mt][nt][2] = s_b[c0];     acc[mt][nt][3] = s_b[c0 + 1];
        }
    #pragma unroll 2
    for (int kc = 0; kc < CH; kc++) {
        const int kw = kc * 8;
        uint32_t ah[4][4], al[4][4];
        #pragma unroll
        for (int mt = 0; mt < 4; mt++) {
            const uint32_t* ap = (const uint32_t*)s_ah + (mrow + mt * 16 + r) * WSL + kw + q;
            const uint32_t* lp = (const uint32_t*)s_al + (mrow + mt * 16 + r) * WSL + kw + q;
            ah[mt][0] = ap[0]; ah[mt][1] = ap[8 * WSL]; ah[mt][2] = ap[4]; ah[mt][3] = ap[8 * WSL + 4];
            al[mt][0] = lp[0]; al[mt][1] = lp[8 * WSL]; al[mt][2] = lp[4]; al[mt][3] = lp[8 * WSL + 4];
        }
        #pragma unroll
        for (int nt = 0; nt < NT; nt++) {
            const uint32_t* bh = (const uint32_t*)s_wh + (nwb + nt * 8 + r) * WSL + kw + q;
            const uint32_t* bl = (const uint32_t*)s_wl + (nwb + nt * 8 + r) * WSL + kw + q;
            uint32_t bh0 = bh[0], bh1 = bh[4], bl0 = bl[0], bl1 = bl[4];
            #pragma unroll
            for (int mt = 0; mt < 4; mt++) {
                MMA_F16(acc[mt][nt], ah[mt], bh0, bh1);
                MMA_F16(acc[mt][nt], ah[mt], bl0, bl1);
                MMA_F16(acc[mt][nt], al[mt], bh0, bh1);
            }
        }
    }
    #pragma unroll
    for (int mt = 0; mt < 4; mt++)
        #pragma unroll
        for (int nt = 0; nt < NT; nt++)
            #pragma unroll
            for (int rr = 0; rr < 2; rr++) {
                int node = base + mrow + mt * 16 + r + 8 * rr;
                if (node < N) {
                    int c0 = nwb + nt * 8 + 2 * q;
                    float vx = fmaxf(acc[mt][nt][2 * rr + 0], 0.f);
                    float vy = fmaxf(acc[mt][nt][2 * rr + 1], 0.f);
                    if (HOUT) {
                        *(__half2*)((__half*)outp + (size_t)node * KOUT + c0) =
                            __floats2half2_rn(vx, vy);
                    } else {
                        *(float2*)((float*)outp + (size_t)node * KOUT + c0) =
                            make_float2(vx, vy);
                    }
                }
            }
}

// ---------------- host launcher ----------------
static void* symaddr(const void* sym) {
    void* p = nullptr;
    cudaGetSymbolAddress(&p, sym);
    return p;
}

extern "C" void kernel_launch(void* const* d_in, const int* in_sizes, int n_in,
                              void* d_out, int out_size) {
    const float* x   = (const float*)d_in[0];
    const int*   ei  = (const int*)d_in[1];
    const int N = in_sizes[0] / 64;
    const int E = in_sizes[1] / 2;
    const int* src = ei;

    const float* p1pw  = (const float*)d_in[3];
    const float* p1pb  = (const float*)d_in[4];
    const float* p1wih = (const float*)d_in[5];
    const float* p1whh = (const float*)d_in[6];
    const float* p1bih = (const float*)d_in[7];
    const float* p1bhh = (const float*)d_in[8];
    const float* p1llw = (const float*)d_in[9];
    const float* p1llb = (const float*)d_in[10];
    const float* p1lrw = (const float*)d_in[11];
    const float* p2pw  = (const float*)d_in[12];
    const float* p2pb  = (const float*)d_in[13];
    const float* p2wih = (const float*)d_in[14];
    const float* p2whh = (const float*)d_in[15];
    const float* p2bih = (const float*)d_in[16];
    const float* p2bhh = (const float*)d_in[17];
    const float* p2llw = (const float*)d_in[18];
    const float* p2llb = (const float*)d_in[19];
    const float* p2lrw = (const float*)d_in[20];
    const float* l1w   = (const float*)d_in[21];
    const float* l1b   = (const float*)d_in[22];
    const float* l2w   = (const float*)d_in[23];
    const float* l2b   = (const float*)d_in[24];
    const float* l3w   = (const float*)d_in[25];
    const float* l3b   = (const float*)d_in[26];

    __half* xp  = (__half*)symaddr(g_xp);
    float*  h1  = (float*)symaddr(g_h1);
    float*  h2  = (float*)symaddr(g_h2);
    float*  t1  = (float*)symaddr(g_t1);
    float*  t2  = (float*)symaddr(g_t2);
    __half* wc1 = (__half*)symaddr(g_wc1);
    __half* wc2 = (__half*)symaddr(g_wc2);
    float*  bs1 = (float*)symaddr(g_bs1);
    float*  bs2 = (float*)symaddr(g_bs2);
    __half* wo1h = (__half*)symaddr(g_wo1h); __half* wo1l = (__half*)symaddr(g_wo1l);
    __half* wo2h = (__half*)symaddr(g_wo2h); __half* wo2l = (__half*)symaddr(g_wo2l);
    __half* pT1h = (__half*)symaddr(g_pT1h); __half* pT1l = (__half*)symaddr(g_pT1l);
    __half* pT2h = (__half*)symaddr(g_pT2h); __half* pT2l = (__half*)symaddr(g_pT2l);
    __half* l1h  = (__half*)symaddr(g_l1h);  __half* l1l  = (__half*)symaddr(g_l1l);
    __half* l2h  = (__half*)symaddr(g_l2h);  __half* l2l  = (__half*)symaddr(g_l2l);
    __half* l3h  = (__half*)symaddr(g_l3h);  __half* l3l  = (__half*)symaddr(g_l3l);

    // smem sizes
    const int SM_LSTM = (256 * KH128 + 128 * KH128 + 128 * KH128) * 2 + 256 * 4 + 2048 * 4; // 148480
    const int SM_6464 = (2 * 64 * 72 + 2 * 128 * 72) * 2 + 64 * 4;                          // 55552
    const int SM_L1   = (2 * 192 * 136 + 2 * 128 * 136) * 2 + 192 * 4;                      // 174848
    const int SM_L2   = (2 * 64 * 200 + 2 * 128 * 200) * 2 + 64 * 4;                        // 153856
    cudaFuncSetAttribute(lstm_mma_kernel<64>,        cudaFuncAttributeMaxDynamicSharedMemorySize, SM_LSTM);
    cudaFuncSetAttribute(lstm_mma_kernel<128>,       cudaFuncAttributeMaxDynamicSharedMemorySize, SM_LSTM);
    cudaFuncSetAttribute(mma_linear<64, 64, true>,   cudaFuncAttributeMaxDynamicSharedMemorySize, SM_6464);
    cudaFuncSetAttribute(mma_linear<64, 64, false>,  cudaFuncAttributeMaxDynamicSharedMemorySize, SM_6464);
    cudaFuncSetAttribute(mma_linear<128, 192, false>, cudaFuncAttributeMaxDynamicSharedMemorySize, SM_L1);
    cudaFuncSetAttribute(mma_linear<192, 64, false>, cudaFuncAttributeMaxDynamicSharedMemorySize, SM_L2);

    // --- fused weight prep ---
    k_prep_all<<<544, 256>>>(p1wih, p1whh, p1bih, p1bhh,
                             p2wih, p2whh, p2bih, p2bhh,
                             p1llw, p1lrw, p2llw, p2lrw,
                             p1pw, p2pw, l1w, l2w, l3w);

    const int NB = (N + 127) / 128;

    // --- layer 1 ---
    mma_linear<64, 64, true><<<NB, 256, SM_6464>>>(x, pT1h, pT1l, p1pb, xp, N);
    lstm_mma_kernel<64><<<NB, 256, SM_LSTM>>>(xp, x, src, wc1, bs1, wo1h, wo1l, p1llb, h1, N);
    // --- layer 2 ---
    mma_linear<64, 64, true><<<NB, 256, SM_6464>>>(h1, pT2h, pT2l, p2pb, xp, N);
    lstm_mma_kernel<128><<<NB, 256, SM_LSTM>>>(xp, h1, src, wc2, bs2, wo2h, wo2l, p2llb, h2, N);
    // --- MLP head ---
    mma_linear<128, 192, false><<<NB, 256, SM_L1>>>(h2, l1h, l1l, l1b, t1, N);
    mma_linear<192, 64, false><<<NB, 256, SM_L2>>>(t1, l2h, l2l, l2b, t2, N);
    mma_linear<64, 64, false><<<NB, 256, SM_6464>>>(t2, l3h, l3l, l3b, d_out, N);

    // --- edge_index passthrough if the output buffer holds it ---
    long hsz = (long)N * 64;
    if ((long)out_size > hsz) {
        long remaining = (long)out_size - hsz;
        int count = (int)((remaining < (long)2 * E) ? remaining : (long)2 * E);
        k_edge_copy<<<(count + 255) / 256, 256>>>(ei, (float*)d_out + hsz, count);
    }
}

// round 8
// speedup vs baseline: 2.7017x; 1.3090x over previous
#include <cuda_runtime.h>
#include <cuda_fp16.h>
#include <cstdint>

// Problem constants (fixed-shape problem)
#define MAXN 50000
#define KDEG 16

// half strides: pad 8 halves (16B) -> word-stride ≡ 4 (mod 32) -> conflict-free frags
#define KH128 136
#define WS128 68

// ---------------- scratch (device globals: allocation-free) ----------------
__device__ __half g_xp [MAXN * 64];    // projected feats, fp16
__device__ float  g_h1 [MAXN * 64];
__device__ float  g_h2 [MAXN * 128];
__device__ float  g_t1 [MAXN * 192];
__device__ float  g_t2 [MAXN * 64];

__device__ __half g_wc1 [256 * 128];   // permuted LSTM weights [pcol][k], fp16
__device__ __half g_wc2 [256 * 128];
__device__ float  g_bs1 [256];
__device__ float  g_bs2 [256];
__device__ __half g_wo1h[64 * 128],  g_wo1l[64 * 128];    // SAGE out [o][k] hi/lo
__device__ __half g_wo2h[128 * 128], g_wo2l[128 * 128];
__device__ __half g_pT1h[64 * 64],   g_pT1l[64 * 64];     // [o][k] hi/lo (torch layout)
__device__ __half g_pT2h[64 * 64],   g_pT2l[64 * 64];
__device__ __half g_l1h [192 * 128], g_l1l [192 * 128];
__device__ __half g_l2h [64 * 192],  g_l2l [64 * 192];
__device__ __half g_l3h [64 * 64],   g_l3l [64 * 64];

// ---------------- helpers ----------------
__device__ __forceinline__ float tanha(float x) {
    float y;
    asm("tanh.approx.f32 %0, %1;" : "=f"(y) : "f"(x));
    return y;
}
__device__ __forceinline__ float sigt(float x) {
    return fmaf(tanha(0.5f * x), 0.5f, 0.5f);
}

#define MMA_F16(D, A, b0, b1)                                                   \
    asm volatile("mma.sync.aligned.m16n8k16.row.col.f32.f16.f16.f32 "           \
                 "{%0,%1,%2,%3}, {%4,%5,%6,%7}, {%8,%9}, {%0,%1,%2,%3};"        \
                 : "+f"(D[0]), "+f"(D[1]), "+f"(D[2]), "+f"(D[3])               \
                 : "r"(A[0]), "r"(A[1]), "r"(A[2]), "r"(A[3]), "r"(b0), "r"(b1));

// Gate-column permutation: each thread's accumulator fragment owns the full
// (i,f,g,o) quadruple for its hidden units.
__device__ __forceinline__ int perm_orig_col(int p) {
    int nj = p >> 6, rr = p & 63;
    int tp = rr >> 4, r2 = rr & 15;
    int half_ = r2 >> 3, r3 = r2 & 7;
    int q = r3 >> 1, low = r3 & 1;
    int gate = half_ * 2 + low;             // 0=i 1=f 2=g 3=o
    int jg = nj * 16 + q * 4 + tp;
    return gate * 64 + jg;
}

__device__ __forceinline__ void wsplit(__half* hi, __half* lo, int idx, float v) {
    __half h = __float2half_rn(v);
    hi[idx] = h;
    lo[idx] = __float2half_rn(v - __half2float(h));
}

// ---------------- single fused prep kernel ----------------
__global__ void k_prep_all(
    const float* p1wih, const float* p1whh, const float* p1bih, const float* p1bhh,
    const float* p2wih, const float* p2whh, const float* p2bih, const float* p2bhh,
    const float* p1llw, const float* p1lrw, const float* p2llw, const float* p2lrw,
    const float* p1pw, const float* p2pw,
    const float* l1w, const float* l2w, const float* l3w) {
    int b = blockIdx.x, t = threadIdx.x;
    if (b < 128) {                       // wc1: 256x128 halves
        int idx = b * 256 + t;
        int p = idx >> 7, k = idx & 127;
        int g = perm_orig_col(p);
        g_wc1[idx] = __float2half_rn(k < 64 ? p1wih[g * 64 + k] : p1whh[g * 64 + (k - 64)]);
        if (idx < 256) { int g2 = perm_orig_col(idx); g_bs1[idx] = p1bih[g2] + p1bhh[g2]; }
    } else if (b < 256) {                // wc2
        int idx = (b - 128) * 256 + t;
        int p = idx >> 7, k = idx & 127;
        int g = perm_orig_col(p);
        g_wc2[idx] = __float2half_rn(k < 64 ? p2wih[g * 64 + k] : p2whh[g * 64 + (k - 64)]);
        if (idx < 256) { int g2 = perm_orig_col(idx); g_bs2[idx] = p2bih[g2] + p2bhh[g2]; }
    } else if (b < 288) {                // wo1: 64x128
        int idx = (b - 256) * 256 + t;
        int o = idx >> 7, k = idx & 127;
        wsplit(g_wo1h, g_wo1l, idx, k < 64 ? p1lrw[o * 64 + k] : p1llw[o * 64 + (k - 64)]);
    } else if (b < 352) {                // wo2: 128x128
        int idx = (b - 288) * 256 + t;
        int o = idx >> 7, k = idx & 127;
        wsplit(g_wo2h, g_wo2l, idx, k < 64 ? p2lrw[o * 64 + k] : p2llw[o * 64 + (k - 64)]);
    } else if (b < 368) {                // pT1
        int idx = (b - 352) * 256 + t;
        wsplit(g_pT1h, g_pT1l, idx, p1pw[idx]);
    } else if (b < 384) {                // pT2
        int idx = (b - 368) * 256 + t;
        wsplit(g_pT2h, g_pT2l, idx, p2pw[idx]);
    } else if (b < 480) {                // l1
        int idx = (b - 384) * 256 + t;
        wsplit(g_l1h, g_l1l, idx, l1w[idx]);
    } else if (b < 528) {                // l2
        int idx = (b - 480) * 256 + t;
        wsplit(g_l2h, g_l2l, idx, l2w[idx]);
    } else {                             // l3
        int idx = (b - 528) * 256 + t;
        wsplit(g_l3h, g_l3l, idx, l3w[idx]);
    }
}

__global__ void k_edge_copy(const int* __restrict__ ei, float* __restrict__ out, int count) {
    int i = blockIdx.x * blockDim.x + threadIdx.x;
    if (i < count) out[i] = (float)ei[i];
}

// ---------------- fused LSTM-SAGE kernel (fp16 m16n8k16, M=64, 2 CTA/SM) ----------------
// Block = 64 nodes, 256 threads = 8 warps, warp grid 2(m32) x 4(n64).
// 109.5 KB smem -> 2 blocks/SM: one block's MUFU activation phase overlaps the
// other block's HMMA GEMM phase with no barrier coupling.
template<int OUT>
__global__ __launch_bounds__(256, 2)
void lstm_mma_kernel(const __half* __restrict__ xp,
                     const float*  __restrict__ xin,
                     const int*    __restrict__ src,
                     const __half* __restrict__ wcat,   // [256][128] permuted
                     const float*  __restrict__ bias,   // [256] permuted
                     const __half* __restrict__ wohi,   // [OUT][128]
                     const __half* __restrict__ wolo,
                     const float*  __restrict__ ob,
                     float* __restrict__ out,
                     int N) {
    extern __shared__ __half smh[];
    __half* s_w   = smh;                        // 256*KH128 (LSTM W; reused for wo hi/lo)
    __half* s_in  = s_w + 256 * KH128;          // 64*KH128 : [x_t | h] (hi plane)
    __half* s_lo  = s_in + 64 * KH128;          // 64*KH128 : epilogue lo plane
    float*  s_b   = (float*)(s_lo + 64 * KH128);   // 256
    int*    s_src = (int*)(s_b + 256);          // 1024

    const int tx = threadIdx.x;
    const int base = blockIdx.x * 64;
    const int lane = tx & 31, w = tx >> 5;
    const int mg = w >> 2, nj = w & 3;
    const int nwb = nj * 64;
    const int mrow = mg * 32;
    const int r = lane >> 2, q = lane & 3;

    // LSTM weights -> smem [p][k], padded rows
    for (int i = tx; i < 4096; i += 256) {               // 256 rows * 16 uint4
        int row = i >> 4, c = i & 15;
        ((uint4*)(s_w + row * KH128))[c] = ((const uint4*)wcat)[i];
    }
    s_b[tx] = bias[tx];
    for (int i = tx; i < 1024; i += 256) {
        int node = base + (i >> 4);
        s_src[i] = (node < N) ? src[node * KDEG + (i & 15)] : 0;
    }
    // zero s_in + s_lo (h cols start at 0; lo plane h cols stay 0)
    for (int i = tx; i < (64 * KH128) / 4; i += 256) {
        ((uint2*)s_in)[i] = make_uint2(0u, 0u);
        ((uint2*)s_lo)[i] = make_uint2(0u, 0u);
    }
    __syncthreads();

    float bs0[8], bs1[8];
    #pragma unroll
    for (int nt = 0; nt < 8; nt++) {
        bs0[nt] = s_b[nwb + nt * 8 + 2 * q];
        bs1[nt] = s_b[nwb + nt * 8 + 2 * q + 1];
    }
    float cst[2][4][2];
    #pragma unroll
    for (int a = 0; a < 2; a++)
        #pragma unroll
        for (int bb = 0; bb < 4; bb++) { cst[a][bb][0] = 0.f; cst[a][bb][1] = 0.f; }

    // gather x_t: 64 rows * 16 uint2 = 1024 over 256 threads
    auto gather = [&](int t) {
        #pragma unroll
        for (int i = 0; i < 4; i++) {
            int idx = tx + i * 256;
            int n = idx >> 4, c = idx & 15;
            uint2 v = *(const uint2*)(xp + (size_t)s_src[n * KDEG + t] * 64 + c * 4);
            *(uint2*)(s_in + n * KH128 + c * 4) = v;
        }
    };

    gather(0);

    for (int t = 0; t < KDEG; t++) {
        __syncthreads();   // gather + h writes visible

        float acc[2][8][4];
        #pragma unroll
        for (int mt = 0; mt < 2; mt++)
            #pragma unroll
            for (int nt = 0; nt < 8; nt++) {
                acc[mt][nt][0] = bs0[nt]; acc[mt][nt][1] = bs1[nt];
                acc[mt][nt][2] = bs0[nt]; acc[mt][nt][3] = bs1[nt];
            }

        #pragma unroll 2
        for (int kc = 0; kc < 8; kc++) {           // K chunks of 16
            const int kw = kc * 8;                 // word offset
            uint32_t afr[2][4];
            #pragma unroll
            for (int mt = 0; mt < 2; mt++) {
                const uint32_t* ap = (const uint32_t*)s_in + (mrow + mt * 16 + r) * WS128 + kw + q;
                afr[mt][0] = ap[0];
                afr[mt][1] = ap[8 * WS128];
                afr[mt][2] = ap[4];
                afr[mt][3] = ap[8 * WS128 + 4];
            }
            #pragma unroll
            for (int nt = 0; nt < 8; nt++) {
                const uint32_t* bp = (const uint32_t*)s_w + (nwb + nt * 8 + r) * WS128 + kw + q;
                uint32_t b0 = bp[0], b1 = bp[4];
                MMA_F16(acc[0][nt], afr[0], b0, b1);
                MMA_F16(acc[1][nt], afr[1], b0, b1);
            }
        }
        __syncthreads();   // s_in reads done

        // activation + h writeback (fp16x4 packed)
        #pragma unroll
        for (int mt = 0; mt < 2; mt++) {
            #pragma unroll
            for (int rr = 0; rr < 2; rr++) {
                float hv[4];
                #pragma unroll
                for (int tp = 0; tp < 4; tp++) {
                    float iv = acc[mt][2 * tp][rr * 2 + 0];
                    float fv = acc[mt][2 * tp][rr * 2 + 1];
                    float gv = acc[mt][2 * tp + 1][rr * 2 + 0];
                    float ov = acc[mt][2 * tp + 1][rr * 2 + 1];
                    float c = sigt(fv) * cst[mt][tp][rr] + sigt(iv) * tanha(gv);
                    cst[mt][tp][rr] = c;
                    hv[tp] = sigt(ov) * tanha(c);
                }
                int row = mrow + mt * 16 + r + 8 * rr;
                __half2* dst = (__half2*)(s_in + row * KH128 + 64 + nj * 16 + q * 4);
                dst[0] = __floats2half2_rn(hv[0], hv[1]);
                dst[1] = __floats2half2_rn(hv[2], hv[3]);
            }
        }
        if (t + 1 < KDEG) gather(t + 1);   // x cols, disjoint from h cols
    }
    __syncthreads();   // all s_w reads done before overwrite

    // ---- fused SAGE output, split fp16: out = relu([x||h]*Wo^T + ob) ----
    constexpr int NT2 = OUT / 32;
    const int nwb2 = nj * (OUT / 4);
    __half* s_wlo = s_w + OUT * KH128;

    for (int i = tx; i < OUT * 16; i += 256) {           // OUT rows * 16 uint4
        int row = i >> 4, c = i & 15;
        ((uint4*)(s_w + row * KH128))[c]   = ((const uint4*)wohi)[i];
        ((uint4*)(s_wlo + row * KH128))[c] = ((const uint4*)wolo)[i];
    }
    for (int i = tx; i < OUT; i += 256) s_b[i] = ob[i];
    // xin -> hi/lo planes (x cols 0..63); h cols: hi already in s_in, lo zero
    #pragma unroll
    for (int i = 0; i < 4; i++) {
        int idx = tx + i * 256;                          // 64 rows * 16 float4
        int n = idx >> 4, c = idx & 15;
        int node = base + n;
        float4 v = make_float4(0.f, 0.f, 0.f, 0.f);
        if (node < N) v = ((const float4*)(xin + (size_t)node * 64))[c];
        __half2 h0 = __floats2half2_rn(v.x, v.y), h1 = __floats2half2_rn(v.z, v.w);
        float2 f0 = __half22float2(h0), f1 = __half22float2(h1);
        __half2* dh = (__half2*)(s_in + n * KH128 + c * 4);
        __half2* dl = (__half2*)(s_lo + n * KH128 + c * 4);
        dh[0] = h0; dh[1] = h1;
        dl[0] = __floats2half2_rn(v.x - f0.x, v.y - f0.y);
        dl[1] = __floats2half2_rn(v.z - f1.x, v.w - f1.y);
    }
    __syncthreads();

    float a2[2][NT2][4];
    #pragma unroll
    for (int mt = 0; mt < 2; mt++)
        #pragma unroll
        for (int nt = 0; nt < NT2; nt++) {
            int c0 = nwb2 + nt * 8 + 2 * q;
            a2[mt][nt][0] = s_b[c0];     a2[mt][nt][1] = s_b[c0 + 1];
            a2[mt][nt][2] = s_b[c0];     a2[mt][nt][3] = s_b[c0 + 1];
        }
    #pragma unroll 2
    for (int kc = 0; kc < 8; kc++) {
        const int kw = kc * 8;
        uint32_t ah[2][4], al[2][4];
        #pragma unroll
        for (int mt = 0; mt < 2; mt++) {
            const uint32_t* ap = (const uint32_t*)s_in + (mrow + mt * 16 + r) * WS128 + kw + q;
            const uint32_t* lp = (const uint32_t*)s_lo + (mrow + mt * 16 + r) * WS128 + kw + q;
            ah[mt][0] = ap[0]; ah[mt][1] = ap[8 * WS128]; ah[mt][2] = ap[4]; ah[mt][3] = ap[8 * WS128 + 4];
            al[mt][0] = lp[0]; al[mt][1] = lp[8 * WS128]; al[mt][2] = lp[4]; al[mt][3] = lp[8 * WS128 + 4];
        }
        #pragma unroll
        for (int nt = 0; nt < NT2; nt++) {
            const uint32_t* bh = (const uint32_t*)s_w   + (nwb2 + nt * 8 + r) * WS128 + kw + q;
            const uint32_t* bl = (const uint32_t*)s_wlo + (nwb2 + nt * 8 + r) * WS128 + kw + q;
            uint32_t bh0 = bh[0], bh1 = bh[4], bl0 = bl[0], bl1 = bl[4];
            #pragma unroll
            for (int mt = 0; mt < 2; mt++) {
                MMA_F16(a2[mt][nt], ah[mt], bh0, bh1);
                MMA_F16(a2[mt][nt], ah[mt], bl0, bl1);
                MMA_F16(a2[mt][nt], al[mt], bh0, bh1);
            }
        }
    }
    #pragma unroll
    for (int mt = 0; mt < 2; mt++)
        #pragma unroll
        for (int nt = 0; nt < NT2; nt++)
            #pragma unroll
            for (int rr = 0; rr < 2; rr++) {
                int node = base + mrow + mt * 16 + r + 8 * rr;
                if (node < N) {
                    int c0 = nwb2 + nt * 8 + 2 * q;
                    float2 v;
                    v.x = fmaxf(a2[mt][nt][2 * rr + 0], 0.f);
                    v.y = fmaxf(a2[mt][nt][2 * rr + 1], 0.f);
                    *(float2*)(out + (size_t)node * OUT + c0) = v;
                }
            }
}

// ---------------- split-fp16 MMA linear + relu ----------------
template<int KIN, int KOUT, bool HOUT>
__global__ __launch_bounds__(256, 1)
void mma_linear(const float* __restrict__ A,
                const __half* __restrict__ Whi, const __half* __restrict__ Wlo,
                const float* __restrict__ bias, void* __restrict__ outp, int N) {
    constexpr int KH = KIN + 8, WSL = KH / 2, CH = KIN / 16;
    constexpr int NT = KOUT / 32;
    extern __shared__ __half sh[];
    __half* s_wh = sh;                        // KOUT*KH
    __half* s_wl = s_wh + KOUT * KH;
    __half* s_ah = s_wl + KOUT * KH;          // 128*KH
    __half* s_al = s_ah + 128 * KH;
    float*  s_b  = (float*)(s_al + 128 * KH);

    const int tx = threadIdx.x, base = blockIdx.x * 128;
    const int lane = tx & 31, w = tx >> 5;
    const int mg = w >> 2, nj = w & 3;
    const int r = lane >> 2, q = lane & 3;
    const int mrow = mg * 64, nwb = nj * (KOUT / 4);

    for (int i = tx; i < KOUT * (KIN / 8); i += 256) {
        int row = i / (KIN / 8), c = i % (KIN / 8);
        ((uint4*)(s_wh + row * KH))[c] = ((const uint4*)Whi)[i];
        ((uint4*)(s_wl + row * KH))[c] = ((const uint4*)Wlo)[i];
    }
    for (int i = tx; i < KOUT; i += 256) s_b[i] = bias[i];
    for (int i = tx; i < 128 * (KIN / 4); i += 256) {
        int n = i / (KIN / 4), c = i % (KIN / 4);
        int node = base + n;
        float4 v = make_float4(0.f, 0.f, 0.f, 0.f);
        if (node < N) v = ((const float4*)(A + (size_t)node * KIN))[c];
        __half2 h0 = __floats2half2_rn(v.x, v.y), h1 = __floats2half2_rn(v.z, v.w);
        float2 f0 = __half22float2(h0), f1 = __half22float2(h1);
        __half2* dh = (__half2*)(s_ah + n * KH + c * 4);
        __half2* dl = (__half2*)(s_al + n * KH + c * 4);
        dh[0] = h0; dh[1] = h1;
        dl[0] = __floats2half2_rn(v.x - f0.x, v.y - f0.y);
        dl[1] = __floats2half2_rn(v.z - f1.x, v.w - f1.y);
    }
    __syncthreads();

    float acc[4][NT][4];
    #pragma unroll
    for (int mt = 0; mt < 4; mt++)
        #pragma unroll
        for (int nt = 0; nt < NT; nt++) {
            int c0 = nwb + nt * 8 + 2 * q;
            acc[mt][nt][0] = s_b[c0];     acc[mt][nt][1] = s_b[c0 + 1];
            acc[mt][nt][2] = s_b[c0];     acc[mt][nt][3] = s_b[c0 + 1];
        }
    #pragma unroll 2
    for (int kc = 0; kc < CH; kc++) {
        const int kw = kc * 8;
        uint32_t ah[4][4], al[4][4];
        #pragma unroll
        for (int mt = 0; mt < 4; mt++) {
            const uint32_t* ap = (const uint32_t*)s_ah + (mrow + mt * 16 + r) * WSL + kw + q;
            const uint32_t* lp = (const uint32_t*)s_al + (mrow + mt * 16 + r) * WSL + kw + q;
            ah[mt][0] = ap[0]; ah[mt][1] = ap[8 * WSL]; ah[mt][2] = ap[4]; ah[mt][3] = ap[8 * WSL + 4];
            al[mt][0] = lp[0]; al[mt][1] = lp[8 * WSL]; al[mt][2] = lp[4]; al[mt][3] = lp[8 * WSL + 4];
        }
        #pragma unroll
        for (int nt = 0; nt < NT; nt++) {
            const uint32_t* bh = (const uint32_t*)s_wh + (nwb + nt * 8 + r) * WSL + kw + q;
            const uint32_t* bl = (const uint32_t*)s_wl + (nwb + nt * 8 + r) * WSL + kw + q;
            uint32_t bh0 = bh[0], bh1 = bh[4], bl0 = bl[0], bl1 = bl[4];
            #pragma unroll
            for (int mt = 0; mt < 4; mt++) {
                MMA_F16(acc[mt][nt], ah[mt], bh0, bh1);
                MMA_F16(acc[mt][nt], ah[mt], bl0, bl1);
                MMA_F16(acc[mt][nt], al[mt], bh0, bh1);
            }
        }
    }
    #pragma unroll
    for (int mt = 0; mt < 4; mt++)
        #pragma unroll
        for (int nt = 0; nt < NT; nt++)
            #pragma unroll
            for (int rr = 0; rr < 2; rr++) {
                int node = base + mrow + mt * 16 + r + 8 * rr;
                if (node < N) {
                    int c0 = nwb + nt * 8 + 2 * q;
                    float vx = fmaxf(acc[mt][nt][2 * rr + 0], 0.f);
                    float vy = fmaxf(acc[mt][nt][2 * rr + 1], 0.f);
                    if (HOUT) {
                        *(__half2*)((__half*)outp + (size_t)node * KOUT + c0) =
                            __floats2half2_rn(vx, vy);
                    } else {
                        *(float2*)((float*)outp + (size_t)node * KOUT + c0) =
                            make_float2(vx, vy);
                    }
                }
            }
}

// ---------------- host launcher ----------------
static void* symaddr(const void* sym) {
    void* p = nullptr;
    cudaGetSymbolAddress(&p, sym);
    return p;
}

extern "C" void kernel_launch(void* const* d_in, const int* in_sizes, int n_in,
                              void* d_out, int out_size) {
    const float* x   = (const float*)d_in[0];
    const int*   ei  = (const int*)d_in[1];
    const int N = in_sizes[0] / 64;
    const int E = in_sizes[1] / 2;
    const int* src = ei;

    const float* p1pw  = (const float*)d_in[3];
    const float* p1pb  = (const float*)d_in[4];
    const float* p1wih = (const float*)d_in[5];
    const float* p1whh = (const float*)d_in[6];
    const float* p1bih = (const float*)d_in[7];
    const float* p1bhh = (const float*)d_in[8];
    const float* p1llw = (const float*)d_in[9];
    const float* p1llb = (const float*)d_in[10];
    const float* p1lrw = (const float*)d_in[11];
    const float* p2pw  = (const float*)d_in[12];
    const float* p2pb  = (const float*)d_in[13];
    const float* p2wih = (const float*)d_in[14];
    const float* p2whh = (const float*)d_in[15];
    const float* p2bih = (const float*)d_in[16];
    const float* p2bhh = (const float*)d_in[17];
    const float* p2llw = (const float*)d_in[18];
    const float* p2llb = (const float*)d_in[19];
    const float* p2lrw = (const float*)d_in[20];
    const float* l1w   = (const float*)d_in[21];
    const float* l1b   = (const float*)d_in[22];
    const float* l2w   = (const float*)d_in[23];
    const float* l2b   = (const float*)d_in[24];
    const float* l3w   = (const float*)d_in[25];
    const float* l3b   = (const float*)d_in[26];

    __half* xp  = (__half*)symaddr(g_xp);
    float*  h1  = (float*)symaddr(g_h1);
    float*  h2  = (float*)symaddr(g_h2);
    float*  t1  = (float*)symaddr(g_t1);
    float*  t2  = (float*)symaddr(g_t2);
    __half* wc1 = (__half*)symaddr(g_wc1);
    __half* wc2 = (__half*)symaddr(g_wc2);
    float*  bs1 = (float*)symaddr(g_bs1);
    float*  bs2 = (float*)symaddr(g_bs2);
    __half* wo1h = (__half*)symaddr(g_wo1h); __half* wo1l = (__half*)symaddr(g_wo1l);
    __half* wo2h = (__half*)symaddr(g_wo2h); __half* wo2l = (__half*)symaddr(g_wo2l);
    __half* pT1h = (__half*)symaddr(g_pT1h); __half* pT1l = (__half*)symaddr(g_pT1l);
    __half* pT2h = (__half*)symaddr(g_pT2h); __half* pT2l = (__half*)symaddr(g_pT2l);
    __half* l1h  = (__half*)symaddr(g_l1h);  __half* l1l  = (__half*)symaddr(g_l1l);
    __half* l2h  = (__half*)symaddr(g_l2h);  __half* l2l  = (__half*)symaddr(g_l2l);
    __half* l3h  = (__half*)symaddr(g_l3h);  __half* l3l  = (__half*)symaddr(g_l3l);

    // smem sizes
    const int SM_LSTM = (256 * KH128 + 64 * KH128 + 64 * KH128) * 2 + 256 * 4 + 1024 * 4;   // 109568
    const int SM_6464 = (2 * 64 * 72 + 2 * 128 * 72) * 2 + 64 * 4;                          // 55552
    const int SM_L1   = (2 * 192 * 136 + 2 * 128 * 136) * 2 + 192 * 4;                      // 174848
    const int SM_L2   = (2 * 64 * 200 + 2 * 128 * 200) * 2 + 64 * 4;                        // 153856
    cudaFuncSetAttribute(lstm_mma_kernel<64>,        cudaFuncAttributeMaxDynamicSharedMemorySize, SM_LSTM);
    cudaFuncSetAttribute(lstm_mma_kernel<128>,       cudaFuncAttributeMaxDynamicSharedMemorySize, SM_LSTM);
    cudaFuncSetAttribute(mma_linear<64, 64, true>,   cudaFuncAttributeMaxDynamicSharedMemorySize, SM_6464);
    cudaFuncSetAttribute(mma_linear<64, 64, false>,  cudaFuncAttributeMaxDynamicSharedMemorySize, SM_6464);
    cudaFuncSetAttribute(mma_linear<128, 192, false>, cudaFuncAttributeMaxDynamicSharedMemorySize, SM_L1);
    cudaFuncSetAttribute(mma_linear<192, 64, false>, cudaFuncAttributeMaxDynamicSharedMemorySize, SM_L2);

    // --- fused weight prep ---
    k_prep_all<<<544, 256>>>(p1wih, p1whh, p1bih, p1bhh,
                             p2wih, p2whh, p2bih, p2bhh,
                             p1llw, p1lrw, p2llw, p2lrw,
                             p1pw, p2pw, l1w, l2w, l3w);

    const int NB128 = (N + 127) / 128;
    const int NB64  = (N + 63) / 64;

    // --- layer 1 ---
    mma_linear<64, 64, true><<<NB128, 256, SM_6464>>>(x, pT1h, pT1l, p1pb, xp, N);
    lstm_mma_kernel<64><<<NB64, 256, SM_LSTM>>>(xp, x, src, wc1, bs1, wo1h, wo1l, p1llb, h1, N);
    // --- layer 2 ---
    mma_linear<64, 64, true><<<NB128, 256, SM_6464>>>(h1, pT2h, pT2l, p2pb, xp, N);
    lstm_mma_kernel<128><<<NB64, 256, SM_LSTM>>>(xp, h1, src, wc2, bs2, wo2h, wo2l, p2llb, h2, N);
    // --- MLP head ---
    mma_linear<128, 192, false><<<NB128, 256, SM_L1>>>(h2, l1h, l1l, l1b, t1, N);
    mma_linear<192, 64, false><<<NB128, 256, SM_L2>>>(t1, l2h, l2l, l2b, t2, N);
    mma_linear<64, 64, false><<<NB128, 256, SM_6464>>>(t2, l3h, l3l, l3b, d_out, N);

    // --- edge_index passthrough if the output buffer holds it ---
    long hsz = (long)N * 64;
    if ((long)out_size > hsz) {
        long remaining = (long)out_size - hsz;
        int count = (int)((remaining < (long)2 * E) ? remaining : (long)2 * E);
        k_edge_copy<<<(count + 255) / 256, 256>>>(ei, (float*)d_out + hsz, count);
    }
}

// round 10
// speedup vs baseline: 2.8292x; 1.0472x over previous
#include <cuda_runtime.h>
#include <cuda_fp16.h>
#include <cstdint>

// Problem constants (fixed-shape problem)
#define MAXN 50000
#define KDEG 16

// half strides: pad 8 halves (16B) -> word-stride ≡ 4 (mod 32) -> conflict-free frags
#define KH128 136
#define WS128 68

// ---------------- scratch (device globals: allocation-free) ----------------
__device__ __half g_xp [MAXN * 64];    // projected feats, fp16
__device__ float  g_h1 [MAXN * 64];
__device__ float  g_h2 [MAXN * 128];
__device__ float  g_t1 [MAXN * 192];
__device__ float  g_t2 [MAXN * 64];

__device__ __half g_wc1 [256 * 128];   // permuted LSTM weights [pcol][k], fp16
__device__ __half g_wc2 [256 * 128];
__device__ float  g_bs1 [256];
__device__ float  g_bs2 [256];
__device__ __half g_wo1h[64 * 128],  g_wo1l[64 * 128];    // SAGE out [o][k] hi/lo
__device__ __half g_wo2h[128 * 128], g_wo2l[128 * 128];
__device__ __half g_pT1h[64 * 64],   g_pT1l[64 * 64];     // [o][k] hi/lo (torch layout)
__device__ __half g_pT2h[64 * 64],   g_pT2l[64 * 64];
__device__ __half g_l1h [192 * 128], g_l1l [192 * 128];
__device__ __half g_l2h [64 * 192],  g_l2l [64 * 192];
__device__ __half g_l3h [64 * 64],   g_l3l [64 * 64];

// ---------------- helpers ----------------
__device__ __forceinline__ __half2 tanh2(__half2 x) {
    __half2 y;
    asm("tanh.approx.f16x2 %0, %1;" : "=r"(*(uint32_t*)&y) : "r"(*(const uint32_t*)&x));
    return y;
}
__device__ __forceinline__ __half2 sig2(__half2 x) {    // sigmoid via tanh, all-f16x2
    const __half2 h05 = __float2half2_rn(0.5f);
    return __hfma2(tanh2(__hmul2(x, h05)), h05, h05);
}

#define MMA_F16(D, A, b0, b1)                                                   \
    asm volatile("mma.sync.aligned.m16n8k16.row.col.f32.f16.f16.f32 "           \
                 "{%0,%1,%2,%3}, {%4,%5,%6,%7}, {%8,%9}, {%0,%1,%2,%3};"        \
                 : "+f"(D[0]), "+f"(D[1]), "+f"(D[2]), "+f"(D[3])               \
                 : "r"(A[0]), "r"(A[1]), "r"(A[2]), "r"(A[3]), "r"(b0), "r"(b1));

#define LDSM_X4(R, addr)                                                        \
    asm volatile("ldmatrix.sync.aligned.m8n8.x4.shared.b16 {%0,%1,%2,%3}, [%4];"\
                 : "=r"((R)[0]), "=r"((R)[1]), "=r"((R)[2]), "=r"((R)[3])       \
                 : "r"(addr));

// Gate-column permutation: each thread's accumulator fragment owns the full
// (i,f,g,o) quadruple for its hidden units.
__device__ __forceinline__ int perm_orig_col(int p) {
    int nj = p >> 6, rr = p & 63;
    int tp = rr >> 4, r2 = rr & 15;
    int half_ = r2 >> 3, r3 = r2 & 7;
    int q = r3 >> 1, low = r3 & 1;
    int gate = half_ * 2 + low;             // 0=i 1=f 2=g 3=o
    int jg = nj * 16 + q * 4 + tp;
    return gate * 64 + jg;
}

__device__ __forceinline__ void wsplit(__half* hi, __half* lo, int idx, float v) {
    __half h = __float2half_rn(v);
    hi[idx] = h;
    lo[idx] = __float2half_rn(v - __half2float(h));
}

// ---------------- single fused prep kernel ----------------
__global__ void k_prep_all(
    const float* p1wih, const float* p1whh, const float* p1bih, const float* p1bhh,
    const float* p2wih, const float* p2whh, const float* p2bih, const float* p2bhh,
    const float* p1llw, const float* p1lrw, const float* p2llw, const float* p2lrw,
    const float* p1pw, const float* p2pw,
    const float* l1w, const float* l2w, const float* l3w) {
    int b = blockIdx.x, t = threadIdx.x;
    if (b < 128) {                       // wc1: 256x128 halves
        int idx = b * 256 + t;
        int p = idx >> 7, k = idx & 127;
        int g = perm_orig_col(p);
        g_wc1[idx] = __float2half_rn(k < 64 ? p1wih[g * 64 + k] : p1whh[g * 64 + (k - 64)]);
        if (idx < 256) { int g2 = perm_orig_col(idx); g_bs1[idx] = p1bih[g2] + p1bhh[g2]; }
    } else if (b < 256) {                // wc2
        int idx = (b - 128) * 256 + t;
        int p = idx >> 7, k = idx & 127;
        int g = perm_orig_col(p);
        g_wc2[idx] = __float2half_rn(k < 64 ? p2wih[g * 64 + k] : p2whh[g * 64 + (k - 64)]);
        if (idx < 256) { int g2 = perm_orig_col(idx); g_bs2[idx] = p2bih[g2] + p2bhh[g2]; }
    } else if (b < 288) {                // wo1: 64x128
        int idx = (b - 256) * 256 + t;
        int o = idx >> 7, k = idx & 127;
        wsplit(g_wo1h, g_wo1l, idx, k < 64 ? p1lrw[o * 64 + k] : p1llw[o * 64 + (k - 64)]);
    } else if (b < 352) {                // wo2: 128x128
        int idx = (b - 288) * 256 + t;
        int o = idx >> 7, k = idx & 127;
        wsplit(g_wo2h, g_wo2l, idx, k < 64 ? p2lrw[o * 64 + k] : p2llw[o * 64 + (k - 64)]);
    } else if (b < 368) {                // pT1
        int idx = (b - 352) * 256 + t;
        wsplit(g_pT1h, g_pT1l, idx, p1pw[idx]);
    } else if (b < 384) {                // pT2
        int idx = (b - 368) * 256 + t;
        wsplit(g_pT2h, g_pT2l, idx, p2pw[idx]);
    } else if (b < 480) {                // l1
        int idx = (b - 384) * 256 + t;
        wsplit(g_l1h, g_l1l, idx, l1w[idx]);
    } else if (b < 528) {                // l2
        int idx = (b - 480) * 256 + t;
        wsplit(g_l2h, g_l2l, idx, l2w[idx]);
    } else {                             // l3
        int idx = (b - 528) * 256 + t;
        wsplit(g_l3h, g_l3l, idx, l3w[idx]);
    }
}

__global__ void k_edge_copy(const int* __restrict__ ei, float* __restrict__ out, int count) {
    int i = blockIdx.x * blockDim.x + threadIdx.x;
    if (i < count) out[i] = (float)ei[i];
}

// ---------------- fused LSTM-SAGE kernel (fp16 m16n8k16, M=64, 2 CTA/SM) ----------------
// Block = 64 nodes, 256 threads = 8 warps, warp grid 2(m32) x 4(n64).
// f16x2 activations (tanh.approx.f16x2, c-state fp32), ldmatrix fragment loads.
template<int OUT>
__global__ __launch_bounds__(256, 2)
void lstm_mma_kernel(const __half* __restrict__ xp,
                     const float*  __restrict__ xin,
                     const int*    __restrict__ src,
                     const __half* __restrict__ wcat,   // [256][128] permuted
                     const float*  __restrict__ bias,   // [256] permuted
                     const __half* __restrict__ wohi,   // [OUT][128]
                     const __half* __restrict__ wolo,
                     const float*  __restrict__ ob,
                     float* __restrict__ out,
                     int N) {
    extern __shared__ __half smh[];
    __half* s_w   = smh;                        // 256*KH128 (LSTM W; reused for wo hi/lo)
    __half* s_in  = s_w + 256 * KH128;          // 64*KH128 : [x_t | h] (hi plane)
    __half* s_lo  = s_in + 64 * KH128;          // 64*KH128 : epilogue lo plane
    float*  s_b   = (float*)(s_lo + 64 * KH128);   // 256
    int*    s_src = (int*)(s_b + 256);          // 1024

    const int tx = threadIdx.x;
    const int base = blockIdx.x * 64;
    const int lane = tx & 31, w = tx >> 5;
    const int mg = w >> 2, nj = w & 3;
    const int nwb = nj * 64;
    const int mrow = mg * 32;
    const int r = lane >> 2, q = lane & 3;

    // LSTM weights -> smem [p][k], padded rows
    for (int i = tx; i < 4096; i += 256) {               // 256 rows * 16 uint4
        int row = i >> 4, c = i & 15;
        ((uint4*)(s_w + row * KH128))[c] = ((const uint4*)wcat)[i];
    }
    s_b[tx] = bias[tx];
    for (int i = tx; i < 1024; i += 256) {
        int node = base + (i >> 4);
        s_src[i] = (node < N) ? src[node * KDEG + (i & 15)] : 0;
    }
    // zero s_in + s_lo (h cols start at 0; lo plane h cols stay 0)
    for (int i = tx; i < (64 * KH128) / 4; i += 256) {
        ((uint2*)s_in)[i] = make_uint2(0u, 0u);
        ((uint2*)s_lo)[i] = make_uint2(0u, 0u);
    }
    __syncthreads();

    float bs0[8], bs1[8];
    #pragma unroll
    for (int nt = 0; nt < 8; nt++) {
        bs0[nt] = s_b[nwb + nt * 8 + 2 * q];
        bs1[nt] = s_b[nwb + nt * 8 + 2 * q + 1];
    }
    float cst[2][4][2];
    #pragma unroll
    for (int a = 0; a < 2; a++)
        #pragma unroll
        for (int bb = 0; bb < 4; bb++) { cst[a][bb][0] = 0.f; cst[a][bb][1] = 0.f; }

    // ldmatrix per-lane base addresses (byte, shared space)
    const uint32_t s_in_u = (uint32_t)__cvta_generic_to_shared(s_in);
    const uint32_t s_w_u  = (uint32_t)__cvta_generic_to_shared(s_w);
    const int tile = lane >> 3, lrow = lane & 7;
    uint32_t aaddr[2], baddr[4];
    #pragma unroll
    for (int mt = 0; mt < 2; mt++)       // A: reg order a0(r,k0) a1(r+8,k0) a2(r,k8) a3(r+8,k8)
        aaddr[mt] = s_in_u + 2 * ((mrow + mt * 16 + (tile & 1) * 8 + lrow) * KH128 + (tile >> 1) * 8);
    #pragma unroll
    for (int np = 0; np < 4; np++)       // B: reg order b0(n,k0) b1(n,k8) b0'(n+8,k0) b1'(n+8,k8)
        baddr[np] = s_w_u + 2 * ((nwb + np * 16 + (tile >> 1) * 8 + lrow) * KH128 + (tile & 1) * 8);

    // gather x_t: 64 rows * 16 uint2 = 1024 over 256 threads
    auto gather = [&](int t) {
        #pragma unroll
        for (int i = 0; i < 4; i++) {
            int idx = tx + i * 256;
            int n = idx >> 4, c = idx & 15;
            uint2 v = *(const uint2*)(xp + (size_t)s_src[n * KDEG + t] * 64 + c * 4);
            *(uint2*)(s_in + n * KH128 + c * 4) = v;
        }
    };

    gather(0);

    for (int t = 0; t < KDEG; t++) {
        __syncthreads();   // gather + h writes visible

        float acc[2][8][4];
        #pragma unroll
        for (int mt = 0; mt < 2; mt++)
            #pragma unroll
            for (int nt = 0; nt < 8; nt++) {
                acc[mt][nt][0] = bs0[nt]; acc[mt][nt][1] = bs1[nt];
                acc[mt][nt][2] = bs0[nt]; acc[mt][nt][3] = bs1[nt];
            }

        #pragma unroll 2
        for (int kc = 0; kc < 8; kc++) {           // K chunks of 16 (32B per row-chunk)
            const uint32_t ko = kc * 32;
            uint32_t af[2][4];
            LDSM_X4(af[0], aaddr[0] + ko);
            LDSM_X4(af[1], aaddr[1] + ko);
            #pragma unroll
            for (int np = 0; np < 4; np++) {
                uint32_t bf[4];
                LDSM_X4(bf, baddr[np] + ko);
                MMA_F16(acc[0][2 * np],     af[0], bf[0], bf[1]);
                MMA_F16(acc[1][2 * np],     af[1], bf[0], bf[1]);
                MMA_F16(acc[0][2 * np + 1], af[0], bf[2], bf[3]);
                MMA_F16(acc[1][2 * np + 1], af[1], bf[2], bf[3]);
            }
        }
        __syncthreads();   // s_in reads done

        // activation: f16x2 tanh path, c-state fp32, h written as half2
        #pragma unroll
        for (int mt = 0; mt < 2; mt++) {
            #pragma unroll
            for (int rr = 0; rr < 2; rr++) {
                int row = mrow + mt * 16 + r + 8 * rr;
                __half2* dst = (__half2*)(s_in + row * KH128 + 64 + nj * 16 + q * 4);
                #pragma unroll
                for (int p = 0; p < 2; p++) {      // tp pair (2p, 2p+1) -> adjacent cols
                    int t0 = 2 * p, t1 = 2 * p + 1;
                    __half2 i2 = __floats2half2_rn(acc[mt][2 * t0][rr * 2 + 0], acc[mt][2 * t1][rr * 2 + 0]);
                    __half2 f2 = __floats2half2_rn(acc[mt][2 * t0][rr * 2 + 1], acc[mt][2 * t1][rr * 2 + 1]);
                    __half2 g2 = __floats2half2_rn(acc[mt][2 * t0 + 1][rr * 2 + 0], acc[mt][2 * t1 + 1][rr * 2 + 0]);
                    __half2 o2 = __floats2half2_rn(acc[mt][2 * t0 + 1][rr * 2 + 1], acc[mt][2 * t1 + 1][rr * 2 + 1]);
                    __half2 si = sig2(i2), sf = sig2(f2), so = sig2(o2), tg = tanh2(g2);
                    float2 fi = __half22float2(si), ff = __half22float2(sf), fg = __half22float2(tg);
                    float c0 = ff.x * cst[mt][t0][rr] + fi.x * fg.x;
                    float c1 = ff.y * cst[mt][t1][rr] + fi.y * fg.y;
                    cst[mt][t0][rr] = c0; cst[mt][t1][rr] = c1;
                    __half2 tc = tanh2(__floats2half2_rn(c0, c1));
                    dst[p] = __hmul2(so, tc);
                }
            }
        }
        if (t + 1 < KDEG) gather(t + 1);   // x cols, disjoint from h cols
    }
    __syncthreads();   // all s_w reads done before overwrite

    // ---- fused SAGE output, split fp16: out = relu([x||h]*Wo^T + ob) ----
    constexpr int NT2 = OUT / 32;
    const int nwb2 = nj * (OUT / 4);
    __half* s_wlo = s_w + OUT * KH128;

    for (int i = tx; i < OUT * 16; i += 256) {           // OUT rows * 16 uint4
        int row = i >> 4, c = i & 15;
        ((uint4*)(s_w + row * KH128))[c]   = ((const uint4*)wohi)[i];
        ((uint4*)(s_wlo + row * KH128))[c] = ((const uint4*)wolo)[i];
    }
    for (int i = tx; i < OUT; i += 256) s_b[i] = ob[i];
    // xin -> hi/lo planes (x cols 0..63); h cols: hi already in s_in, lo zero
    #pragma unroll
    for (int i = 0; i < 4; i++) {
        int idx = tx + i * 256;                          // 64 rows * 16 float4
        int n = idx >> 4, c = idx & 15;
        int node = base + n;
        float4 v = make_float4(0.f, 0.f, 0.f, 0.f);
        if (node < N) v = ((const float4*)(xin + (size_t)node * 64))[c];
        __half2 h0 = __floats2half2_rn(v.x, v.y), h1 = __floats2half2_rn(v.z, v.w);
        float2 f0 = __half22float2(h0), f1 = __half22float2(h1);
        __half2* dh = (__half2*)(s_in + n * KH128 + c * 4);
        __half2* dl = (__half2*)(s_lo + n * KH128 + c * 4);
        dh[0] = h0; dh[1] = h1;
        dl[0] = __floats2half2_rn(v.x - f0.x, v.y - f0.y);
        dl[1] = __floats2half2_rn(v.z - f1.x, v.w - f1.y);
    }
    __syncthreads();

    float a2[2][NT2][4];
    #pragma unroll
    for (int mt = 0; mt < 2; mt++)
        #pragma unroll
        for (int nt = 0; nt < NT2; nt++) {
            int c0 = nwb2 + nt * 8 + 2 * q;
            a2[mt][nt][0] = s_b[c0];     a2[mt][nt][1] = s_b[c0 + 1];
            a2[mt][nt][2] = s_b[c0];     a2[mt][nt][3] = s_b[c0 + 1];
        }
    #pragma unroll 2
    for (int kc = 0; kc < 8; kc++) {
        const int kw = kc * 8;
        uint32_t ah[2][4], al[2][4];
        #pragma unroll
        for (int mt = 0; mt < 2; mt++) {
            const uint32_t* ap = (const uint32_t*)s_in + (mrow + mt * 16 + r) * WS128 + kw + q;
            const uint32_t* lp = (const uint32_t*)s_lo + (mrow + mt * 16 + r) * WS128 + kw + q;
            ah[mt][0] = ap[0]; ah[mt][1] = ap[8 * WS128]; ah[mt][2] = ap[4]; ah[mt][3] = ap[8 * WS128 + 4];
            al[mt][0] = lp[0]; al[mt][1] = lp[8 * WS128]; al[mt][2] = lp[4]; al[mt][3] = lp[8 * WS128 + 4];
        }
        #pragma unroll
        for (int nt = 0; nt < NT2; nt++) {
            const uint32_t* bh = (const uint32_t*)s_w   + (nwb2 + nt * 8 + r) * WS128 + kw + q;
            const uint32_t* bl = (const uint32_t*)s_wlo + (nwb2 + nt * 8 + r) * WS128 + kw + q;
            uint32_t bh0 = bh[0], bh1 = bh[4], bl0 = bl[0], bl1 = bl[4];
            #pragma unroll
            for (int mt = 0; mt < 2; mt++) {
                MMA_F16(a2[mt][nt], ah[mt], bh0, bh1);
                MMA_F16(a2[mt][nt], ah[mt], bl0, bl1);
                MMA_F16(a2[mt][nt], al[mt], bh0, bh1);
            }
        }
    }
    #pragma unroll
    for (int mt = 0; mt < 2; mt++)
        #pragma unroll
        for (int nt = 0; nt < NT2; nt++)
            #pragma unroll
            for (int rr = 0; rr < 2; rr++) {
                int node = base + mrow + mt * 16 + r + 8 * rr;
                if (node < N) {
                    int c0 = nwb2 + nt * 8 + 2 * q;
                    float2 v;
                    v.x = fmaxf(a2[mt][nt][2 * rr + 0], 0.f);
                    v.y = fmaxf(a2[mt][nt][2 * rr + 1], 0.f);
                    *(float2*)(out + (size_t)node * OUT + c0) = v;
                }
            }
}

// ---------------- split-fp16 MMA linear + relu ----------------
template<int KIN, int KOUT, bool HOUT>
__global__ __launch_bounds__(256, 1)
void mma_linear(const float* __restrict__ A,
                const __half* __restrict__ Whi, const __half* __restrict__ Wlo,
                const float* __restrict__ bias, void* __restrict__ outp, int N) {
    constexpr int KH = KIN + 8, WSL = KH / 2, CH = KIN / 16;
    constexpr int NT = KOUT / 32;
    extern __shared__ __half sh[];
    __half* s_wh = sh;                        // KOUT*KH
    __half* s_wl = s_wh + KOUT * KH;
    __half* s_ah = s_wl + KOUT * KH;          // 128*KH
    __half* s_al = s_ah + 128 * KH;
    float*  s_b  = (float*)(s_al + 128 * KH);

    const int tx = threadIdx.x, base = blockIdx.x * 128;
    const int lane = tx & 31, w = tx >> 5;
    const int mg = w >> 2, nj = w & 3;
    const int r = lane >> 2, q = lane & 3;
    const int mrow = mg * 64, nwb = nj * (KOUT / 4);

    for (int i = tx; i < KOUT * (KIN / 8); i += 256) {
        int row = i / (KIN / 8), c = i % (KIN / 8);
        ((uint4*)(s_wh + row * KH))[c] = ((const uint4*)Whi)[i];
        ((uint4*)(s_wl + row * KH))[c] = ((const uint4*)Wlo)[i];
    }
    for (int i = tx; i < KOUT; i += 256) s_b[i] = bias[i];
    for (int i = tx; i < 128 * (KIN / 4); i += 256) {
        int n = i / (KIN / 4), c = i % (KIN / 4);
        int node = base + n;
        float4 v = make_float4(0.f, 0.f, 0.f, 0.f);
        if (node < N) v = ((const float4*)(A + (size_t)node * KIN))[c];
        __half2 h0 = __floats2half2_rn(v.x, v.y), h1 = __floats2half2_rn(v.z, v.w);
        float2 f0 = __half22float2(h0), f1 = __half22float2(h1);
        __half2* dh = (__half2*)(s_ah + n * KH + c * 4);
        __half2* dl = (__half2*)(s_al + n * KH + c * 4);
        dh[0] = h0; dh[1] = h1;
        dl[0] = __floats2half2_rn(v.x - f0.x, v.y - f0.y);
        dl[1] = __floats2half2_rn(v.z - f1.x, v.w - f1.y);
    }
    __syncthreads();

    float acc[4][NT][4];
    #pragma unroll
    for (int mt = 0; mt < 4; mt++)
        #pragma unroll
        for (int nt = 0; nt < NT; nt++) {
            int c0 = nwb + nt * 8 + 2 * q;
            acc[mt][nt][0] = s_b[c0];     acc[mt][nt][1] = s_b[c0 + 1];
            acc[mt][nt][2] = s_b[c0];     acc[mt][nt][3] = s_b[c0 + 1];
        }
    #pragma unroll 2
    for (int kc = 0; kc < CH; kc++) {
        const int kw = kc * 8;
        uint32_t ah[4][4], al[4][4];
        #pragma unroll
        for (int mt = 0; mt < 4; mt++) {
            const uint32_t* ap = (const uint32_t*)s_ah + (mrow + mt * 16 + r) * WSL + kw + q;
            const uint32_t* lp = (const uint32_t*)s_al + (mrow + mt * 16 + r) * WSL + kw + q;
            ah[mt][0] = ap[0]; ah[mt][1] = ap[8 * WSL]; ah[mt][2] = ap[4]; ah[mt][3] = ap[8 * WSL + 4];
            al[mt][0] = lp[0]; al[mt][1] = lp[8 * WSL]; al[mt][2] = lp[4]; al[mt][3] = lp[8 * WSL + 4];
        }
        #pragma unroll
        for (int nt = 0; nt < NT; nt++) {
            const uint32_t* bh = (const uint32_t*)s_wh + (nwb + nt * 8 + r) * WSL + kw + q;
            const uint32_t* bl = (const uint32_t*)s_wl + (nwb + nt * 8 + r) * WSL + kw + q;
            uint32_t bh0 = bh[0], bh1 = bh[4], bl0 = bl[0], bl1 = bl[4];
            #pragma unroll
            for (int mt = 0; mt < 4; mt++) {
                MMA_F16(acc[mt][nt], ah[mt], bh0, bh1);
                MMA_F16(acc[mt][nt], ah[mt], bl0, bl1);
                MMA_F16(acc[mt][nt], al[mt], bh0, bh1);
            }
        }
    }
    #pragma unroll
    for (int mt = 0; mt < 4; mt++)
        #pragma unroll
        for (int nt = 0; nt < NT; nt++)
            #pragma unroll
            for (int rr = 0; rr < 2; rr++) {
                int node = base + mrow + mt * 16 + r + 8 * rr;
                if (node < N) {
                    int c0 = nwb + nt * 8 + 2 * q;
                    float vx = fmaxf(acc[mt][nt][2 * rr + 0], 0.f);
                    float vy = fmaxf(acc[mt][nt][2 * rr + 1], 0.f);
                    if (HOUT) {
                        *(__half2*)((__half*)outp + (size_t)node * KOUT + c0) =
                            __floats2half2_rn(vx, vy);
                    } else {
                        *(float2*)((float*)outp + (size_t)node * KOUT + c0) =
                            make_float2(vx, vy);
                    }
                }
            }
}

// ---------------- host launcher ----------------
static void* symaddr(const void* sym) {
    void* p = nullptr;
    cudaGetSymbolAddress(&p, sym);
    return p;
}

extern "C" void kernel_launch(void* const* d_in, const int* in_sizes, int n_in,
                              void* d_out, int out_size) {
    const float* x   = (const float*)d_in[0];
    const int*   ei  = (const int*)d_in[1];
    const int N = in_sizes[0] / 64;
    const int E = in_sizes[1] / 2;
    const int* src = ei;

    const float* p1pw  = (const float*)d_in[3];
    const float* p1pb  = (const float*)d_in[4];
    const float* p1wih = (const float*)d_in[5];
    const float* p1whh = (const float*)d_in[6];
    const float* p1bih = (const float*)d_in[7];
    const float* p1bhh = (const float*)d_in[8];
    const float* p1llw = (const float*)d_in[9];
    const float* p1llb = (const float*)d_in[10];
    const float* p1lrw = (const float*)d_in[11];
    const float* p2pw  = (const float*)d_in[12];
    const float* p2pb  = (const float*)d_in[13];
    const float* p2wih = (const float*)d_in[14];
    const float* p2whh = (const float*)d_in[15];
    const float* p2bih = (const float*)d_in[16];
    const float* p2bhh = (const float*)d_in[17];
    const float* p2llw = (const float*)d_in[18];
    const float* p2llb = (const float*)d_in[19];
    const float* p2lrw = (const float*)d_in[20];
    const float* l1w   = (const float*)d_in[21];
    const float* l1b   = (const float*)d_in[22];
    const float* l2w   = (const float*)d_in[23];
    const float* l2b   = (const float*)d_in[24];
    const float* l3w   = (const float*)d_in[25];
    const float* l3b   = (const float*)d_in[26];

    __half* xp  = (__half*)symaddr(g_xp);
    float*  h1  = (float*)symaddr(g_h1);
    float*  h2  = (float*)symaddr(g_h2);
    float*  t1  = (float*)symaddr(g_t1);
    float*  t2  = (float*)symaddr(g_t2);
    __half* wc1 = (__half*)symaddr(g_wc1);
    __half* wc2 = (__half*)symaddr(g_wc2);
    float*  bs1 = (float*)symaddr(g_bs1);
    float*  bs2 = (float*)symaddr(g_bs2);
    __half* wo1h = (__half*)symaddr(g_wo1h); __half* wo1l = (__half*)symaddr(g_wo1l);
    __half* wo2h = (__half*)symaddr(g_wo2h); __half* wo2l = (__half*)symaddr(g_wo2l);
    __half* pT1h = (__half*)symaddr(g_pT1h); __half* pT1l = (__half*)symaddr(g_pT1l);
    __half* pT2h = (__half*)symaddr(g_pT2h); __half* pT2l = (__half*)symaddr(g_pT2l);
    __half* l1h  = (__half*)symaddr(g_l1h);  __half* l1l  = (__half*)symaddr(g_l1l);
    __half* l2h  = (__half*)symaddr(g_l2h);  __half* l2l  = (__half*)symaddr(g_l2l);
    __half* l3h  = (__half*)symaddr(g_l3h);  __half* l3l  = (__half*)symaddr(g_l3l);

    // smem sizes
    const int SM_LSTM = (256 * KH128 + 64 * KH128 + 64 * KH128) * 2 + 256 * 4 + 1024 * 4;   // 109568
    const int SM_6464 = (2 * 64 * 72 + 2 * 128 * 72) * 2 + 64 * 4;                          // 55552
    const int SM_L1   = (2 * 192 * 136 + 2 * 128 * 136) * 2 + 192 * 4;                      // 174848
    const int SM_L2   = (2 * 64 * 200 + 2 * 128 * 200) * 2 + 64 * 4;                        // 153856
    cudaFuncSetAttribute(lstm_mma_kernel<64>,        cudaFuncAttributeMaxDynamicSharedMemorySize, SM_LSTM);
    cudaFuncSetAttribute(lstm_mma_kernel<128>,       cudaFuncAttributeMaxDynamicSharedMemorySize, SM_LSTM);
    cudaFuncSetAttribute(mma_linear<64, 64, true>,   cudaFuncAttributeMaxDynamicSharedMemorySize, SM_6464);
    cudaFuncSetAttribute(mma_linear<64, 64, false>,  cudaFuncAttributeMaxDynamicSharedMemorySize, SM_6464);
    cudaFuncSetAttribute(mma_linear<128, 192, false>, cudaFuncAttributeMaxDynamicSharedMemorySize, SM_L1);
    cudaFuncSetAttribute(mma_linear<192, 64, false>, cudaFuncAttributeMaxDynamicSharedMemorySize, SM_L2);

    // --- fused weight prep ---
    k_prep_all<<<544, 256>>>(p1wih, p1whh, p1bih, p1bhh,
                             p2wih, p2whh, p2bih, p2bhh,
                             p1llw, p1lrw, p2llw, p2lrw,
                             p1pw, p2pw, l1w, l2w, l3w);

    const int NB128 = (N + 127) / 128;
    const int NB64  = (N + 63) / 64;

    // --- layer 1 ---
    mma_linear<64, 64, true><<<NB128, 256, SM_6464>>>(x, pT1h, pT1l, p1pb, xp, N);
    lstm_mma_kernel<64><<<NB64, 256, SM_LSTM>>>(xp, x, src, wc1, bs1, wo1h, wo1l, p1llb, h1, N);
    // --- layer 2 ---
    mma_linear<64, 64, true><<<NB128, 256, SM_6464>>>(h1, pT2h, pT2l, p2pb, xp, N);
    lstm_mma_kernel<128><<<NB64, 256, SM_LSTM>>>(xp, h1, src, wc2, bs2, wo2h, wo2l, p2llb, h2, N);
    // --- MLP head ---
    mma_linear<128, 192, false><<<NB128, 256, SM_L1>>>(h2, l1h, l1l, l1b, t1, N);
    mma_linear<192, 64, false><<<NB128, 256, SM_L2>>>(t1, l2h, l2l, l2b, t2, N);
    mma_linear<64, 64, false><<<NB128, 256, SM_6464>>>(t2, l3h, l3l, l3b, d_out, N);

    // --- edge_index passthrough if the output buffer holds it ---
    long hsz = (long)N * 64;
    if ((long)out_size > hsz) {
        long remaining = (long)out_size - hsz;
        int count = (int)((remaining < (long)2 * E) ? remaining : (long)2 * E);
        k_edge_copy<<<(count + 255) / 256, 256>>>(ei, (float*)d_out + hsz, count);
    }
}